// round 4
// baseline (speedup 1.0000x reference)
#include <cuda_runtime.h>
#include <math.h>

#define TOK   4096          // B*N = 4*1024
#define DIM_  1024
#define HID_  4096

// Scratch (allocation-free rule: __device__ globals)
__device__ float g_H  [(size_t)TOK * DIM_];
__device__ float g_QKV[(size_t)TOK * 3 * DIM_];
__device__ float g_O  [(size_t)TOK * DIM_];
__device__ float g_X1 [(size_t)TOK * DIM_];
__device__ float g_G  [(size_t)TOK * HID_];

// Packed f32x2 FMA: acc = a*b + acc (elementwise on 2 lanes)
__device__ __forceinline__ void ffma2(float2& acc, const float2& a, const float2& b) {
    unsigned long long& d = reinterpret_cast<unsigned long long&>(acc);
    const unsigned long long& x = reinterpret_cast<const unsigned long long&>(a);
    const unsigned long long& y = reinterpret_cast<const unsigned long long&>(b);
    asm("fma.rn.f32x2 %0, %1, %2, %0;" : "+l"(d) : "l"(x), "l"(y));
}

// ---------------------------------------------------------------------------
// LayerNorm: one block per row (1024 cols), 256 threads, float4 per thread
// ---------------------------------------------------------------------------
__global__ void ln_kernel(const float* __restrict__ x, const float* __restrict__ g,
                          const float* __restrict__ b, float* __restrict__ out) {
    __shared__ float red[2][8];
    int row = blockIdx.x, tid = threadIdx.x;
    const float4* xr = (const float4*)(x + (size_t)row * DIM_);
    float4 v = xr[tid];
    float s  = v.x + v.y + v.z + v.w;
    float sq = v.x*v.x + v.y*v.y + v.z*v.z + v.w*v.w;
    #pragma unroll
    for (int o = 16; o > 0; o >>= 1) {
        s  += __shfl_xor_sync(0xffffffffu, s,  o);
        sq += __shfl_xor_sync(0xffffffffu, sq, o);
    }
    int wid = tid >> 5, lid = tid & 31;
    if (lid == 0) { red[0][wid] = s; red[1][wid] = sq; }
    __syncthreads();
    s = 0.f; sq = 0.f;
    #pragma unroll
    for (int i = 0; i < 8; i++) { s += red[0][i]; sq += red[1][i]; }
    float mean = s * (1.0f / DIM_);
    float var  = sq * (1.0f / DIM_) - mean * mean;
    float rstd = rsqrtf(var + 1e-5f);
    float4 gg = ((const float4*)g)[tid];
    float4 bb = ((const float4*)b)[tid];
    float4 o4;
    o4.x = (v.x - mean) * rstd * gg.x + bb.x;
    o4.y = (v.y - mean) * rstd * gg.y + bb.y;
    o4.z = (v.z - mean) * rstd * gg.z + bb.z;
    o4.w = (v.w - mean) * rstd * gg.w + bb.w;
    ((float4*)(out + (size_t)row * DIM_))[tid] = o4;
}

// ---------------------------------------------------------------------------
// GEMM: C[M,N] = A[M,K] * B[N,K]^T + bias[N]  (+ epilogue), packed f32x2 math.
//   EPI 0: bias only | EPI 1: bias + exact GELU | EPI 2: bias + residual
// 128x128 tile, BK=16, 256 threads, 8x8 microtile as 8x4 f32x2 packs.
// A stored DUPLICATED in smem so LDS.128 yields two (a,a) packs directly.
// ---------------------------------------------------------------------------
template <int EPI>
__global__ void __launch_bounds__(256, 2)
gemm_tn(const float* __restrict__ A, const float* __restrict__ B,
        const float* __restrict__ bias, const float* __restrict__ res,
        float* __restrict__ C, int M, int N, int K) {
    __shared__ float As[16][256];   // duplicated: As[k][2m]=As[k][2m+1]=A[m,k]
    __shared__ float Bs[16][128];
    const int tid = threadIdx.x;
    const int tx = tid & 15, ty = tid >> 4;
    const float* Ab = A + (size_t)blockIdx.y * 128 * K;
    const float* Bb = B + (size_t)blockIdx.x * 128 * K;

    float2 acc[8][4];
    #pragma unroll
    for (int i = 0; i < 8; i++)
        #pragma unroll
        for (int j = 0; j < 4; j++) acc[i][j] = make_float2(0.f, 0.f);

    for (int k0 = 0; k0 < K; k0 += 16) {
        #pragma unroll
        for (int l = 0; l < 2; l++) {
            int idx = tid + l * 256;          // 0..511
            int row = idx >> 2;               // 0..127
            int kc  = (idx & 3) << 2;         // 0,4,8,12
            float4 va = *(const float4*)(Ab + (size_t)row * K + k0 + kc);
            *(float2*)&As[kc+0][2*row] = make_float2(va.x, va.x);
            *(float2*)&As[kc+1][2*row] = make_float2(va.y, va.y);
            *(float2*)&As[kc+2][2*row] = make_float2(va.z, va.z);
            *(float2*)&As[kc+3][2*row] = make_float2(va.w, va.w);
            float4 vb = *(const float4*)(Bb + (size_t)row * K + k0 + kc);
            Bs[kc+0][row] = vb.x; Bs[kc+1][row] = vb.y;
            Bs[kc+2][row] = vb.z; Bs[kc+3][row] = vb.w;
        }
        __syncthreads();
        #pragma unroll
        for (int kk = 0; kk < 16; kk++) {
            float2 a2[8], b2[4];
            #pragma unroll
            for (int u = 0; u < 4; u++) {
                float4 t = *(float4*)&As[kk][ty * 16 + 4 * u];
                a2[2*u]   = make_float2(t.x, t.y);
                a2[2*u+1] = make_float2(t.z, t.w);
            }
            {
                float4 t0 = *(float4*)&Bs[kk][tx * 8];
                float4 t1 = *(float4*)&Bs[kk][tx * 8 + 4];
                b2[0] = make_float2(t0.x, t0.y); b2[1] = make_float2(t0.z, t0.w);
                b2[2] = make_float2(t1.x, t1.y); b2[3] = make_float2(t1.z, t1.w);
            }
            #pragma unroll
            for (int i = 0; i < 8; i++)
                #pragma unroll
                for (int j = 0; j < 4; j++)
                    ffma2(acc[i][j], a2[i], b2[j]);
        }
        __syncthreads();
    }

    int crow0 = blockIdx.y * 128 + ty * 8;
    int ccol0 = blockIdx.x * 128 + tx * 8;
    float bv[8];
    #pragma unroll
    for (int j = 0; j < 8; j++) bv[j] = bias[ccol0 + j];
    #pragma unroll
    for (int i = 0; i < 8; i++) {
        size_t roff = (size_t)(crow0 + i) * N + ccol0;
        #pragma unroll
        for (int j = 0; j < 4; j++) {
            float v0 = acc[i][j].x + bv[2*j];
            float v1 = acc[i][j].y + bv[2*j+1];
            if (EPI == 1) {
                v0 = 0.5f * v0 * (1.0f + erff(v0 * 0.70710678118654752f));
                v1 = 0.5f * v1 * (1.0f + erff(v1 * 0.70710678118654752f));
            }
            if (EPI == 2) {
                float2 r = *(const float2*)(res + roff + 2*j);
                v0 += r.x; v1 += r.y;
            }
            *(float2*)(C + roff + 2*j) = make_float2(v0, v1);
        }
    }
}

// ---------------------------------------------------------------------------
// Flash attention, fp32, packed f32x2 for the QK GEMM.
// Grid: (64 batch-heads, 8 query tiles of 128). 256 threads.
// Smem floats: Qt[64][256] dup+transposed (16384), Kt[64][128] (8192),
//              Vs[128][64] (8192), Ps[128][128] (16384)  -> 196608 bytes
// ---------------------------------------------------------------------------
__global__ void __launch_bounds__(256, 1)
attn_kernel(const float* __restrict__ QKV, float* __restrict__ O) {
    extern __shared__ float sm[];
    float* Qt = sm;                // 16384 floats: Qt[k][2r]=Qt[k][2r+1]=Q[r,k]*scale
    float* Kt = sm + 16384;        // 8192
    float* Vs = sm + 24576;        // 8192
    float* Ps = sm + 32768;        // 16384
    const int bb = blockIdx.x >> 4, h = blockIdx.x & 15;
    const int q0 = blockIdx.y * 128;
    const int tid = threadIdx.x;
    const int tx = tid & 15, ty = tid >> 4;
    const size_t base = (size_t)bb * 1024 * 3072 + (size_t)h * 64;
    const float scale = 0.125f;    // 64^-0.5

    // Load Q tile (pre-scaled), duplicated + transposed
    for (int i = tid; i < 2048; i += 256) {
        int r = i >> 4, c4 = (i & 15) << 2;
        float4 v = *(const float4*)(QKV + base + (size_t)(q0 + r) * 3072 + c4);
        *(float2*)&Qt[(c4 + 0) * 256 + 2*r] = make_float2(v.x * scale, v.x * scale);
        *(float2*)&Qt[(c4 + 1) * 256 + 2*r] = make_float2(v.y * scale, v.y * scale);
        *(float2*)&Qt[(c4 + 2) * 256 + 2*r] = make_float2(v.z * scale, v.z * scale);
        *(float2*)&Qt[(c4 + 3) * 256 + 2*r] = make_float2(v.w * scale, v.w * scale);
    }

    float m_i[8], l_i[8], o[8][4];
    #pragma unroll
    for (int i = 0; i < 8; i++) {
        m_i[i] = -1e30f; l_i[i] = 0.f;
        #pragma unroll
        for (int j = 0; j < 4; j++) o[i][j] = 0.f;
    }

    for (int kt = 0; kt < 8; kt++) {
        __syncthreads();   // covers Q load on first iter, previous tile readers after
        for (int i = tid; i < 2048; i += 256) {
            int r = i >> 4, c4 = (i & 15) << 2;
            const float* src = QKV + base + (size_t)(kt * 128 + r) * 3072;
            float4 kv = *(const float4*)(src + 1024 + c4);
            Kt[(c4 + 0) * 128 + r] = kv.x;
            Kt[(c4 + 1) * 128 + r] = kv.y;
            Kt[(c4 + 2) * 128 + r] = kv.z;
            Kt[(c4 + 3) * 128 + r] = kv.w;
            *(float4*)&Vs[r * 64 + c4] = *(const float4*)(src + 2048 + c4);
        }
        __syncthreads();

        // S = Qs * K^T  (packed f32x2)
        float2 s2[8][4];
        #pragma unroll
        for (int i = 0; i < 8; i++)
            #pragma unroll
            for (int j = 0; j < 4; j++) s2[i][j] = make_float2(0.f, 0.f);
        for (int kk = 0; kk < 64; kk++) {
            float2 a2[8], b2[4];
            #pragma unroll
            for (int u = 0; u < 4; u++) {
                float4 t = *(float4*)&Qt[kk * 256 + ty * 16 + 4 * u];
                a2[2*u]   = make_float2(t.x, t.y);
                a2[2*u+1] = make_float2(t.z, t.w);
            }
            {
                float4 t0 = *(float4*)&Kt[kk * 128 + tx * 8];
                float4 t1 = *(float4*)&Kt[kk * 128 + tx * 8 + 4];
                b2[0] = make_float2(t0.x, t0.y); b2[1] = make_float2(t0.z, t0.w);
                b2[2] = make_float2(t1.x, t1.y); b2[3] = make_float2(t1.z, t1.w);
            }
            #pragma unroll
            for (int i = 0; i < 8; i++)
                #pragma unroll
                for (int j = 0; j < 4; j++)
                    ffma2(s2[i][j], a2[i], b2[j]);
        }

        // Online softmax (row groups = 16 contiguous lanes sharing ty)
        #pragma unroll
        for (int i = 0; i < 8; i++) {
            float s[8];
            #pragma unroll
            for (int j = 0; j < 4; j++) { s[2*j] = s2[i][j].x; s[2*j+1] = s2[i][j].y; }
            float mx = s[0];
            #pragma unroll
            for (int j = 1; j < 8; j++) mx = fmaxf(mx, s[j]);
            #pragma unroll
            for (int off = 8; off > 0; off >>= 1)
                mx = fmaxf(mx, __shfl_xor_sync(0xffffffffu, mx, off));
            float m_new = fmaxf(m_i[i], mx);
            float corr = __expf(m_i[i] - m_new);
            float p[8], rs = 0.f;
            #pragma unroll
            for (int j = 0; j < 8; j++) { p[j] = __expf(s[j] - m_new); rs += p[j]; }
            #pragma unroll
            for (int off = 8; off > 0; off >>= 1)
                rs += __shfl_xor_sync(0xffffffffu, rs, off);
            l_i[i] = l_i[i] * corr + rs;
            m_i[i] = m_new;
            #pragma unroll
            for (int j = 0; j < 4; j++) o[i][j] *= corr;
            *(float4*)&Ps[(ty * 8 + i) * 128 + tx * 8]     = make_float4(p[0],p[1],p[2],p[3]);
            *(float4*)&Ps[(ty * 8 + i) * 128 + tx * 8 + 4] = make_float4(p[4],p[5],p[6],p[7]);
        }
        __syncwarp();   // Ps rows produced & consumed within the same 16-lane group

        // O += P * V (scalar; p-broadcast can't be cheaply packed)
        for (int kk = 0; kk < 128; kk++) {
            float4 vv = *(float4*)&Vs[kk * 64 + tx * 4];
            #pragma unroll
            for (int i = 0; i < 8; i++) {
                float pp = Ps[(ty * 8 + i) * 128 + kk];
                o[i][0] += pp * vv.x; o[i][1] += pp * vv.y;
                o[i][2] += pp * vv.z; o[i][3] += pp * vv.w;
            }
        }
    }

    #pragma unroll
    for (int i = 0; i < 8; i++) {
        float inv = 1.0f / l_i[i];
        int tok = bb * 1024 + q0 + ty * 8 + i;
        float4 r = make_float4(o[i][0]*inv, o[i][1]*inv, o[i][2]*inv, o[i][3]*inv);
        *(float4*)&O[(size_t)tok * 1024 + h * 64 + tx * 4] = r;
    }
}

// ---------------------------------------------------------------------------
extern "C" void kernel_launch(void* const* d_in, const int* in_sizes, int n_in,
                              void* d_out, int out_size) {
    const float* x      = (const float*)d_in[0];
    const float* ln1_g  = (const float*)d_in[1];
    const float* ln1_b  = (const float*)d_in[2];
    const float* qkv_w  = (const float*)d_in[3];
    const float* qkv_b  = (const float*)d_in[4];
    const float* proj_w = (const float*)d_in[5];
    const float* proj_b = (const float*)d_in[6];
    const float* ln2_g  = (const float*)d_in[7];
    const float* ln2_b  = (const float*)d_in[8];
    const float* fc1_w  = (const float*)d_in[9];
    const float* fc1_b  = (const float*)d_in[10];
    const float* fc2_w  = (const float*)d_in[11];
    const float* fc2_b  = (const float*)d_in[12];
    float* out = (float*)d_out;

    float *H, *QKV, *O, *X1, *G;
    cudaGetSymbolAddress((void**)&H,   g_H);
    cudaGetSymbolAddress((void**)&QKV, g_QKV);
    cudaGetSymbolAddress((void**)&O,   g_O);
    cudaGetSymbolAddress((void**)&X1,  g_X1);
    cudaGetSymbolAddress((void**)&G,   g_G);

    cudaFuncSetAttribute(attn_kernel,
                         cudaFuncAttributeMaxDynamicSharedMemorySize, 196608);

    // 1) LN1
    ln_kernel<<<TOK, 256>>>(x, ln1_g, ln1_b, H);
    // 2) QKV = H @ qkv_w^T + b              [4096, 3072]
    gemm_tn<0><<<dim3(3072/128, TOK/128), 256>>>(H, qkv_w, qkv_b, nullptr, QKV,
                                                 TOK, 3072, DIM_);
    // 3) attention -> O                      [4096, 1024]
    attn_kernel<<<dim3(64, 8), 256, 196608>>>(QKV, O);
    // 4) X1 = x + O @ proj_w^T + b
    gemm_tn<2><<<dim3(DIM_/128, TOK/128), 256>>>(O, proj_w, proj_b, x, X1,
                                                 TOK, DIM_, DIM_);
    // 5) LN2
    ln_kernel<<<TOK, 256>>>(X1, ln2_g, ln2_b, H);
    // 6) G = gelu(H @ fc1_w^T + b)           [4096, 4096]
    gemm_tn<1><<<dim3(HID_/128, TOK/128), 256>>>(H, fc1_w, fc1_b, nullptr, G,
                                                 TOK, HID_, DIM_);
    // 7) out = X1 + G @ fc2_w^T + b
    gemm_tn<2><<<dim3(DIM_/128, TOK/128), 256>>>(G, fc2_w, fc2_b, X1, out,
                                                 TOK, DIM_, HID_);
}

// round 7
// speedup vs baseline: 2.2636x; 2.2636x over previous
#include <cuda_runtime.h>
#include <cuda_bf16.h>
#include <math.h>
#include <stdint.h>

#define TOK   4096
#define DIM_  1024
#define HID_  4096

// ---------------- scratch (__device__ globals; no allocations) -------------
__device__ float          g_QKV [(size_t)TOK * 3 * DIM_];
__device__ float          g_X1  [(size_t)TOK * DIM_];
__device__ __nv_bfloat16  g_Hhi [(size_t)TOK * DIM_];
__device__ __nv_bfloat16  g_Hlo [(size_t)TOK * DIM_];
__device__ __nv_bfloat16  g_Ohi [(size_t)TOK * DIM_];
__device__ __nv_bfloat16  g_Olo [(size_t)TOK * DIM_];
__device__ __nv_bfloat16  g_Ghi [(size_t)TOK * HID_];
__device__ __nv_bfloat16  g_Glo [(size_t)TOK * HID_];
__device__ __nv_bfloat16  g_Wqkv_h[(size_t)3 * DIM_ * DIM_];
__device__ __nv_bfloat16  g_Wqkv_l[(size_t)3 * DIM_ * DIM_];
__device__ __nv_bfloat16  g_Wproj_h[(size_t)DIM_ * DIM_];
__device__ __nv_bfloat16  g_Wproj_l[(size_t)DIM_ * DIM_];
__device__ __nv_bfloat16  g_Wfc1_h[(size_t)HID_ * DIM_];
__device__ __nv_bfloat16  g_Wfc1_l[(size_t)HID_ * DIM_];
__device__ __nv_bfloat16  g_Wfc2_h[(size_t)DIM_ * HID_];
__device__ __nv_bfloat16  g_Wfc2_l[(size_t)DIM_ * HID_];

// ---------------- helpers ---------------------------------------------------
__device__ __forceinline__ uint32_t smem_u32(const void* p) {
    uint32_t a;
    asm("{ .reg .u64 t; cvta.to.shared.u64 t, %1; cvt.u32.u64 %0, t; }"
        : "=r"(a) : "l"(p));
    return a;
}
__device__ __forceinline__ void cp16(uint32_t dst, const void* src) {
    asm volatile("cp.async.cg.shared.global [%0], [%1], 16;" :: "r"(dst), "l"(src));
}
#define CP_COMMIT() asm volatile("cp.async.commit_group;" ::: "memory")
#define CP_WAIT1()  asm volatile("cp.async.wait_group 1;"  ::: "memory")

#define LDSM4(r, addr) \
    asm volatile("ldmatrix.sync.aligned.m8n8.x4.shared.b16 {%0,%1,%2,%3}, [%4];" \
        : "=r"((r)[0]), "=r"((r)[1]), "=r"((r)[2]), "=r"((r)[3]) : "r"(addr))

#define MMA_BF16(c, a, b) \
    asm volatile("mma.sync.aligned.m16n8k16.row.col.f32.bf16.bf16.f32 " \
        "{%0,%1,%2,%3}, {%4,%5,%6,%7}, {%8,%9}, {%0,%1,%2,%3};" \
        : "+f"((c)[0]), "+f"((c)[1]), "+f"((c)[2]), "+f"((c)[3]) \
        : "r"((a)[0]), "r"((a)[1]), "r"((a)[2]), "r"((a)[3]), \
          "r"((b)[0]), "r"((b)[1]))

// split a fp32 pair into packed bf16x2 hi/lo words
__device__ __forceinline__ void split_pair(float v0, float v1, uint32_t& hp, uint32_t& lp) {
    __nv_bfloat162 h2 = __floats2bfloat162_rn(v0, v1);
    float h0 = __bfloat162float(h2.x), h1 = __bfloat162float(h2.y);
    __nv_bfloat162 l2 = __floats2bfloat162_rn(v0 - h0, v1 - h1);
    hp = *reinterpret_cast<uint32_t*>(&h2);
    lp = *reinterpret_cast<uint32_t*>(&l2);
}

// ---------------------------------------------------------------------------
// weight split kernel: fp32 -> bf16 hi/lo
// ---------------------------------------------------------------------------
__global__ void conv_split(const float4* __restrict__ W, uint2* __restrict__ hi,
                           uint2* __restrict__ lo, int n4) {
    int i = blockIdx.x * blockDim.x + threadIdx.x;
    if (i >= n4) return;
    float4 v = W[i];
    uint2 h, l;
    split_pair(v.x, v.y, h.x, l.x);
    split_pair(v.z, v.w, h.y, l.y);
    hi[i] = h; lo[i] = l;
}

// ---------------------------------------------------------------------------
// LayerNorm: one block per row, 256 threads, outputs bf16 hi/lo
// ---------------------------------------------------------------------------
__global__ void ln_kernel(const float* __restrict__ x, const float* __restrict__ g,
                          const float* __restrict__ b,
                          __nv_bfloat16* __restrict__ hi, __nv_bfloat16* __restrict__ lo) {
    __shared__ float red[2][8];
    int row = blockIdx.x, tid = threadIdx.x;
    float4 v = ((const float4*)(x + (size_t)row * DIM_))[tid];
    float s  = v.x + v.y + v.z + v.w;
    float sq = v.x*v.x + v.y*v.y + v.z*v.z + v.w*v.w;
    #pragma unroll
    for (int o = 16; o > 0; o >>= 1) {
        s  += __shfl_xor_sync(0xffffffffu, s,  o);
        sq += __shfl_xor_sync(0xffffffffu, sq, o);
    }
    int wid = tid >> 5, lid = tid & 31;
    if (lid == 0) { red[0][wid] = s; red[1][wid] = sq; }
    __syncthreads();
    s = 0.f; sq = 0.f;
    #pragma unroll
    for (int i = 0; i < 8; i++) { s += red[0][i]; sq += red[1][i]; }
    float mean = s * (1.0f / DIM_);
    float var  = sq * (1.0f / DIM_) - mean * mean;
    float rstd = rsqrtf(var + 1e-5f);
    float4 gg = ((const float4*)g)[tid];
    float4 bb = ((const float4*)b)[tid];
    float o0 = (v.x - mean) * rstd * gg.x + bb.x;
    float o1 = (v.y - mean) * rstd * gg.y + bb.y;
    float o2 = (v.z - mean) * rstd * gg.z + bb.z;
    float o3 = (v.w - mean) * rstd * gg.w + bb.w;
    uint2 h, l;
    split_pair(o0, o1, h.x, l.x);
    split_pair(o2, o3, h.y, l.y);
    size_t off = (size_t)row * DIM_ + tid * 4;
    *(uint2*)(hi + off) = h;
    *(uint2*)(lo + off) = l;
}

// ---------------------------------------------------------------------------
// bf16-split GEMM via mma.sync: C[M,N] = A[M,K] @ B[N,K]^T + bias (+ epilogue)
//   D = Ah*Bh + Ah*Bl + Al*Bh  (fp32 accum)
//   EPI 0: fp32 C = D + bias
//   EPI 1: gelu(D + bias) -> bf16 hi/lo
//   EPI 2: fp32 C = D + bias + res
// 128x128 tile, BK=32, 256 threads (8 warps as 2Mx4N, warp tile 64x32),
// cp.async double buffer. Smem rows: 32 bf16 = 64B data, 80B stride
// (16B-aligned, ldmatrix conflict-free).
// ---------------------------------------------------------------------------
#define ROWB   80
#define ARRB   10240      // 128 * 80
#define STAGEB 40960      // 4 arrays

template <int EPI>
__global__ void __launch_bounds__(256, 1)
gemm_mma(const __nv_bfloat16* __restrict__ Ahi, const __nv_bfloat16* __restrict__ Alo,
         const __nv_bfloat16* __restrict__ Bhi, const __nv_bfloat16* __restrict__ Blo,
         const float* __restrict__ bias, const float* __restrict__ res,
         float* __restrict__ Cf,
         __nv_bfloat16* __restrict__ Chi, __nv_bfloat16* __restrict__ Clo,
         int M, int N, int K) {
    extern __shared__ char smem[];
    const uint32_t sb = smem_u32(smem);
    const int tid = threadIdx.x, wid = tid >> 5, lane = tid & 31;
    const int warpM = wid & 1, warpN = wid >> 1;     // 2 x 4 warps

    const size_t aoff = (size_t)blockIdx.y * 128 * K;
    const size_t boff = (size_t)blockIdx.x * 128 * K;
    const __nv_bfloat16* srcs[4] = {Ahi + aoff, Alo + aoff, Bhi + boff, Blo + boff};

    // per-thread ldmatrix offsets
    const int mat = lane >> 3, l = lane & 7;
    const uint32_t a_off = (uint32_t)((warpM * 64 + (mat & 1) * 8 + l) * ROWB + (mat >> 1) * 16);
    const uint32_t b_off = (uint32_t)((warpN * 32 + (mat >> 1) * 8 + l) * ROWB + (mat & 1) * 16);

    float acc[4][4][4];
    #pragma unroll
    for (int mi = 0; mi < 4; mi++)
        #pragma unroll
        for (int ni = 0; ni < 4; ni++)
            #pragma unroll
            for (int q = 0; q < 4; q++) acc[mi][ni][q] = 0.f;

    const int NC = K >> 5;

    auto fill = [&](int buf, int c) {
        #pragma unroll
        for (int arr = 0; arr < 4; arr++) {
            const __nv_bfloat16* s = srcs[arr];
            #pragma unroll
            for (int q = 0; q < 2; q++) {
                int idx = tid + q * 256;             // 0..511
                int row = idx >> 2, ch = idx & 3;
                cp16(sb + buf * STAGEB + arr * ARRB + row * ROWB + ch * 16,
                     s + (size_t)row * K + c * 32 + ch * 8);
            }
        }
        CP_COMMIT();
    };

    fill(0, 0);
    for (int c = 0; c < NC; c++) {
        const int buf = c & 1;
        if (c + 1 < NC) fill(buf ^ 1, c + 1); else CP_COMMIT();
        CP_WAIT1();
        __syncthreads();

        const uint32_t As  = sb + buf * STAGEB;
        const uint32_t Als = As + ARRB;
        const uint32_t Bs  = As + 2 * ARRB;
        const uint32_t Bls = As + 3 * ARRB;

        #pragma unroll
        for (int ks = 0; ks < 2; ks++) {
            uint32_t ah[4][4], bh[4][2], bl[4][2], t0[4], t1[4];
            #pragma unroll
            for (int mi = 0; mi < 4; mi++)
                LDSM4(ah[mi], As + a_off + mi * (16 * ROWB) + ks * 32);
            LDSM4(t0, Bs + b_off + ks * 32);
            LDSM4(t1, Bs + b_off + 16 * ROWB + ks * 32);
            bh[0][0]=t0[0]; bh[0][1]=t0[1]; bh[1][0]=t0[2]; bh[1][1]=t0[3];
            bh[2][0]=t1[0]; bh[2][1]=t1[1]; bh[3][0]=t1[2]; bh[3][1]=t1[3];
            LDSM4(t0, Bls + b_off + ks * 32);
            LDSM4(t1, Bls + b_off + 16 * ROWB + ks * 32);
            bl[0][0]=t0[0]; bl[0][1]=t0[1]; bl[1][0]=t0[2]; bl[1][1]=t0[3];
            bl[2][0]=t1[0]; bl[2][1]=t1[1]; bl[3][0]=t1[2]; bl[3][1]=t1[3];

            #pragma unroll
            for (int mi = 0; mi < 4; mi++)
                #pragma unroll
                for (int ni = 0; ni < 4; ni++) {
                    MMA_BF16(acc[mi][ni], ah[mi], bh[ni]);
                    MMA_BF16(acc[mi][ni], ah[mi], bl[ni]);
                }
            uint32_t al[4][4];
            #pragma unroll
            for (int mi = 0; mi < 4; mi++)
                LDSM4(al[mi], Als + a_off + mi * (16 * ROWB) + ks * 32);
            #pragma unroll
            for (int mi = 0; mi < 4; mi++)
                #pragma unroll
                for (int ni = 0; ni < 4; ni++)
                    MMA_BF16(acc[mi][ni], al[mi], bh[ni]);
        }
        __syncthreads();
    }

    // epilogue
    const int r0 = blockIdx.y * 128 + warpM * 64 + (lane >> 2);
    const int cb = blockIdx.x * 128 + warpN * 32 + 2 * (lane & 3);
    float bv[4][2];
    #pragma unroll
    for (int ni = 0; ni < 4; ni++) {
        bv[ni][0] = __ldg(bias + cb + ni * 8);
        bv[ni][1] = __ldg(bias + cb + ni * 8 + 1);
    }
    #pragma unroll
    for (int mi = 0; mi < 4; mi++) {
        #pragma unroll
        for (int ni = 0; ni < 4; ni++) {
            int row = r0 + mi * 16;
            int col = cb + ni * 8;
            float v0 = acc[mi][ni][0] + bv[ni][0];
            float v1 = acc[mi][ni][1] + bv[ni][1];
            float v2 = acc[mi][ni][2] + bv[ni][0];
            float v3 = acc[mi][ni][3] + bv[ni][1];
            size_t o0 = (size_t)row * N + col;
            size_t o1 = (size_t)(row + 8) * N + col;
            if (EPI == 1) {
                v0 = 0.5f * v0 * (1.0f + erff(v0 * 0.70710678118654752f));
                v1 = 0.5f * v1 * (1.0f + erff(v1 * 0.70710678118654752f));
                v2 = 0.5f * v2 * (1.0f + erff(v2 * 0.70710678118654752f));
                v3 = 0.5f * v3 * (1.0f + erff(v3 * 0.70710678118654752f));
                uint32_t hp, lp;
                split_pair(v0, v1, hp, lp);
                *(uint32_t*)(Chi + o0) = hp; *(uint32_t*)(Clo + o0) = lp;
                split_pair(v2, v3, hp, lp);
                *(uint32_t*)(Chi + o1) = hp; *(uint32_t*)(Clo + o1) = lp;
            } else {
                if (EPI == 2) {
                    float2 ra = *(const float2*)(res + o0);
                    float2 rb = *(const float2*)(res + o1);
                    v0 += ra.x; v1 += ra.y; v2 += rb.x; v3 += rb.y;
                }
                *(float2*)(Cf + o0) = make_float2(v0, v1);
                *(float2*)(Cf + o1) = make_float2(v2, v3);
            }
        }
    }
}

// ---------------------------------------------------------------------------
// Flash attention, fp32 (round-1 proven version), output split to bf16 hi/lo
// ---------------------------------------------------------------------------
__global__ void __launch_bounds__(256, 1)
attn_kernel(const float* __restrict__ QKV,
            __nv_bfloat16* __restrict__ Ohi, __nv_bfloat16* __restrict__ Olo) {
    extern __shared__ float sm[];
    float* Qs = sm;
    float* Kt = sm + 8192;
    float* Vs = sm + 16384;
    float* Ps = sm + 24576;
    const int bb = blockIdx.x >> 4, h = blockIdx.x & 15;
    const int q0 = blockIdx.y * 128;
    const int tid = threadIdx.x;
    const int tx = tid & 15, ty = tid >> 4;
    const size_t base = (size_t)bb * 1024 * 3072 + (size_t)h * 64;
    const float scale = 0.125f;

    for (int i = tid; i < 2048; i += 256) {
        int r = i >> 4, c4 = (i & 15) << 2;
        float4 v = *(const float4*)(QKV + base + (size_t)(q0 + r) * 3072 + c4);
        v.x *= scale; v.y *= scale; v.z *= scale; v.w *= scale;
        *(float4*)&Qs[r * 64 + c4] = v;
    }

    float m_i[8], l_i[8], o[8][4];
    #pragma unroll
    for (int i = 0; i < 8; i++) {
        m_i[i] = -1e30f; l_i[i] = 0.f;
        #pragma unroll
        for (int j = 0; j < 4; j++) o[i][j] = 0.f;
    }

    for (int kt = 0; kt < 8; kt++) {
        __syncthreads();
        for (int i = tid; i < 2048; i += 256) {
            int r = i >> 4, c4 = (i & 15) << 2;
            const float* src = QKV + base + (size_t)(kt * 128 + r) * 3072;
            float4 kv = *(const float4*)(src + 1024 + c4);
            Kt[(c4 + 0) * 128 + r] = kv.x;
            Kt[(c4 + 1) * 128 + r] = kv.y;
            Kt[(c4 + 2) * 128 + r] = kv.z;
            Kt[(c4 + 3) * 128 + r] = kv.w;
            *(float4*)&Vs[r * 64 + c4] = *(const float4*)(src + 2048 + c4);
        }
        __syncthreads();

        float s[8][8];
        #pragma unroll
        for (int i = 0; i < 8; i++)
            #pragma unroll
            for (int j = 0; j < 8; j++) s[i][j] = 0.f;
        for (int kk = 0; kk < 64; kk++) {
            float a[8];
            #pragma unroll
            for (int i = 0; i < 8; i++) a[i] = Qs[(ty * 8 + i) * 64 + kk];
            float4 b0 = *(float4*)&Kt[kk * 128 + tx * 8];
            float4 b1 = *(float4*)&Kt[kk * 128 + tx * 8 + 4];
            float b[8] = {b0.x,b0.y,b0.z,b0.w,b1.x,b1.y,b1.z,b1.w};
            #pragma unroll
            for (int i = 0; i < 8; i++)
                #pragma unroll
                for (int j = 0; j < 8; j++)
                    s[i][j] += a[i] * b[j];
        }

        #pragma unroll
        for (int i = 0; i < 8; i++) {
            float mx = s[i][0];
            #pragma unroll
            for (int j = 1; j < 8; j++) mx = fmaxf(mx, s[i][j]);
            #pragma unroll
            for (int off = 8; off > 0; off >>= 1)
                mx = fmaxf(mx, __shfl_xor_sync(0xffffffffu, mx, off));
            float m_new = fmaxf(m_i[i], mx);
            float corr = __expf(m_i[i] - m_new);
            float p[8], rs = 0.f;
            #pragma unroll
            for (int j = 0; j < 8; j++) { p[j] = __expf(s[i][j] - m_new); rs += p[j]; }
            #pragma unroll
            for (int off = 8; off > 0; off >>= 1)
                rs += __shfl_xor_sync(0xffffffffu, rs, off);
            l_i[i] = l_i[i] * corr + rs;
            m_i[i] = m_new;
            #pragma unroll
            for (int j = 0; j < 4; j++) o[i][j] *= corr;
            *(float4*)&Ps[(ty * 8 + i) * 128 + tx * 8]     = make_float4(p[0],p[1],p[2],p[3]);
            *(float4*)&Ps[(ty * 8 + i) * 128 + tx * 8 + 4] = make_float4(p[4],p[5],p[6],p[7]);
        }
        __syncwarp();

        for (int kk = 0; kk < 128; kk++) {
            float4 vv = *(float4*)&Vs[kk * 64 + tx * 4];
            #pragma unroll
            for (int i = 0; i < 8; i++) {
                float pp = Ps[(ty * 8 + i) * 128 + kk];
                o[i][0] += pp * vv.x; o[i][1] += pp * vv.y;
                o[i][2] += pp * vv.z; o[i][3] += pp * vv.w;
            }
        }
    }

    #pragma unroll
    for (int i = 0; i < 8; i++) {
        float inv = 1.0f / l_i[i];
        int tok = bb * 1024 + q0 + ty * 8 + i;
        float v0 = o[i][0]*inv, v1 = o[i][1]*inv, v2 = o[i][2]*inv, v3 = o[i][3]*inv;
        uint2 hp, lp;
        split_pair(v0, v1, hp.x, lp.x);
        split_pair(v2, v3, hp.y, lp.y);
        size_t off = (size_t)tok * 1024 + h * 64 + tx * 4;
        *(uint2*)(Ohi + off) = hp;
        *(uint2*)(Olo + off) = lp;
    }
}

// ---------------------------------------------------------------------------
extern "C" void kernel_launch(void* const* d_in, const int* in_sizes, int n_in,
                              void* d_out, int out_size) {
    const float* x      = (const float*)d_in[0];
    const float* ln1_g  = (const float*)d_in[1];
    const float* ln1_b  = (const float*)d_in[2];
    const float* qkv_w  = (const float*)d_in[3];
    const float* qkv_b  = (const float*)d_in[4];
    const float* proj_w = (const float*)d_in[5];
    const float* proj_b = (const float*)d_in[6];
    const float* ln2_g  = (const float*)d_in[7];
    const float* ln2_b  = (const float*)d_in[8];
    const float* fc1_w  = (const float*)d_in[9];
    const float* fc1_b  = (const float*)d_in[10];
    const float* fc2_w  = (const float*)d_in[11];
    const float* fc2_b  = (const float*)d_in[12];
    float* out = (float*)d_out;

    float *QKV, *X1;
    __nv_bfloat16 *Hh,*Hl,*Oh,*Ol,*Gh,*Gl,*Wqh,*Wql,*Wph,*Wpl,*W1h,*W1l,*W2h,*W2l;
    cudaGetSymbolAddress((void**)&QKV, g_QKV);
    cudaGetSymbolAddress((void**)&X1,  g_X1);
    cudaGetSymbolAddress((void**)&Hh,  g_Hhi);  cudaGetSymbolAddress((void**)&Hl, g_Hlo);
    cudaGetSymbolAddress((void**)&Oh,  g_Ohi);  cudaGetSymbolAddress((void**)&Ol, g_Olo);
    cudaGetSymbolAddress((void**)&Gh,  g_Ghi);  cudaGetSymbolAddress((void**)&Gl, g_Glo);
    cudaGetSymbolAddress((void**)&Wqh, g_Wqkv_h); cudaGetSymbolAddress((void**)&Wql, g_Wqkv_l);
    cudaGetSymbolAddress((void**)&Wph, g_Wproj_h); cudaGetSymbolAddress((void**)&Wpl, g_Wproj_l);
    cudaGetSymbolAddress((void**)&W1h, g_Wfc1_h); cudaGetSymbolAddress((void**)&W1l, g_Wfc1_l);
    cudaGetSymbolAddress((void**)&W2h, g_Wfc2_h); cudaGetSymbolAddress((void**)&W2l, g_Wfc2_l);

    const int GSM = 2 * STAGEB;   // 81920
    cudaFuncSetAttribute(gemm_mma<0>, cudaFuncAttributeMaxDynamicSharedMemorySize, GSM);
    cudaFuncSetAttribute(gemm_mma<1>, cudaFuncAttributeMaxDynamicSharedMemorySize, GSM);
    cudaFuncSetAttribute(gemm_mma<2>, cudaFuncAttributeMaxDynamicSharedMemorySize, GSM);
    cudaFuncSetAttribute(attn_kernel, cudaFuncAttributeMaxDynamicSharedMemorySize, 163840);

    // weight splits
    {
        int n4;
        n4 = 3 * DIM_ * DIM_ / 4;
        conv_split<<<(n4 + 255) / 256, 256>>>((const float4*)qkv_w, (uint2*)Wqh, (uint2*)Wql, n4);
        n4 = DIM_ * DIM_ / 4;
        conv_split<<<(n4 + 255) / 256, 256>>>((const float4*)proj_w, (uint2*)Wph, (uint2*)Wpl, n4);
        n4 = HID_ * DIM_ / 4;
        conv_split<<<(n4 + 255) / 256, 256>>>((const float4*)fc1_w, (uint2*)W1h, (uint2*)W1l, n4);
        n4 = DIM_ * HID_ / 4;
        conv_split<<<(n4 + 255) / 256, 256>>>((const float4*)fc2_w, (uint2*)W2h, (uint2*)W2l, n4);
    }

    // 1) LN1 -> H (bf16 hi/lo)
    ln_kernel<<<TOK, 256>>>(x, ln1_g, ln1_b, Hh, Hl);
    // 2) QKV = H @ qkv_w^T + b  (fp32 out)
    gemm_mma<0><<<dim3(3072/128, TOK/128), 256, GSM>>>(Hh, Hl, Wqh, Wql, qkv_b,
                                                       nullptr, QKV, nullptr, nullptr,
                                                       TOK, 3072, DIM_);
    // 3) attention -> O (bf16 hi/lo)
    attn_kernel<<<dim3(64, 8), 256, 163840>>>(QKV, Oh, Ol);
    // 4) X1 = x + O @ proj_w^T + b
    gemm_mma<2><<<dim3(DIM_/128, TOK/128), 256, GSM>>>(Oh, Ol, Wph, Wpl, proj_b,
                                                       x, X1, nullptr, nullptr,
                                                       TOK, DIM_, DIM_);
    // 5) LN2 -> H
    ln_kernel<<<TOK, 256>>>(X1, ln2_g, ln2_b, Hh, Hl);
    // 6) G = gelu(H @ fc1_w^T + b) (bf16 hi/lo out)
    gemm_mma<1><<<dim3(HID_/128, TOK/128), 256, GSM>>>(Hh, Hl, W1h, W1l, fc1_b,
                                                       nullptr, nullptr, Gh, Gl,
                                                       TOK, HID_, DIM_);
    // 7) out = X1 + G @ fc2_w^T + b
    gemm_mma<2><<<dim3(DIM_/128, TOK/128), 256, GSM>>>(Gh, Gl, W2h, W2l, fc2_b,
                                                       X1, out, nullptr, nullptr,
                                                       TOK, DIM_, HID_);
}

// round 8
// speedup vs baseline: 2.4326x; 1.0747x over previous
#include <cuda_runtime.h>
#include <cuda_bf16.h>
#include <math.h>
#include <stdint.h>

#define TOK   4096
#define DIM_  1024
#define HID_  4096

// ---------------- scratch (__device__ globals; no allocations) -------------
__device__ float          g_QKV [(size_t)TOK * 3 * DIM_];
__device__ float          g_X1  [(size_t)TOK * DIM_];
__device__ __nv_bfloat16  g_Hhi [(size_t)TOK * DIM_];
__device__ __nv_bfloat16  g_Hlo [(size_t)TOK * DIM_];
__device__ __nv_bfloat16  g_Ohi [(size_t)TOK * DIM_];
__device__ __nv_bfloat16  g_Olo [(size_t)TOK * DIM_];
__device__ __nv_bfloat16  g_Ghi [(size_t)TOK * HID_];
__device__ __nv_bfloat16  g_Glo [(size_t)TOK * HID_];
__device__ __nv_bfloat16  g_Wqkv_h[(size_t)3 * DIM_ * DIM_];
__device__ __nv_bfloat16  g_Wqkv_l[(size_t)3 * DIM_ * DIM_];
__device__ __nv_bfloat16  g_Wproj_h[(size_t)DIM_ * DIM_];
__device__ __nv_bfloat16  g_Wproj_l[(size_t)DIM_ * DIM_];
__device__ __nv_bfloat16  g_Wfc1_h[(size_t)HID_ * DIM_];
__device__ __nv_bfloat16  g_Wfc1_l[(size_t)HID_ * DIM_];
__device__ __nv_bfloat16  g_Wfc2_h[(size_t)DIM_ * HID_];
__device__ __nv_bfloat16  g_Wfc2_l[(size_t)DIM_ * HID_];

// ---------------- helpers ---------------------------------------------------
__device__ __forceinline__ uint32_t smem_u32(const void* p) {
    uint32_t a;
    asm("{ .reg .u64 t; cvta.to.shared.u64 t, %1; cvt.u32.u64 %0, t; }"
        : "=r"(a) : "l"(p));
    return a;
}
__device__ __forceinline__ void cp16(uint32_t dst, const void* src) {
    asm volatile("cp.async.cg.shared.global [%0], [%1], 16;" :: "r"(dst), "l"(src));
}
#define CP_COMMIT() asm volatile("cp.async.commit_group;" ::: "memory")
#define CP_WAIT1()  asm volatile("cp.async.wait_group 1;"  ::: "memory")

#define LDSM4(r, addr) \
    asm volatile("ldmatrix.sync.aligned.m8n8.x4.shared.b16 {%0,%1,%2,%3}, [%4];" \
        : "=r"((r)[0]), "=r"((r)[1]), "=r"((r)[2]), "=r"((r)[3]) : "r"(addr))

#define MMA_BF16(c, a, b) \
    asm volatile("mma.sync.aligned.m16n8k16.row.col.f32.bf16.bf16.f32 " \
        "{%0,%1,%2,%3}, {%4,%5,%6,%7}, {%8,%9}, {%0,%1,%2,%3};" \
        : "+f"((c)[0]), "+f"((c)[1]), "+f"((c)[2]), "+f"((c)[3]) \
        : "r"((a)[0]), "r"((a)[1]), "r"((a)[2]), "r"((a)[3]), \
          "r"((b)[0]), "r"((b)[1]))

// split a fp32 pair into packed bf16x2 hi/lo words
__device__ __forceinline__ void split_pair(float v0, float v1, uint32_t& hp, uint32_t& lp) {
    __nv_bfloat162 h2 = __floats2bfloat162_rn(v0, v1);
    float h0 = __bfloat162float(h2.x), h1 = __bfloat162float(h2.y);
    __nv_bfloat162 l2 = __floats2bfloat162_rn(v0 - h0, v1 - h1);
    hp = *reinterpret_cast<uint32_t*>(&h2);
    lp = *reinterpret_cast<uint32_t*>(&l2);
}

// ---------------------------------------------------------------------------
// combined weight split kernel: fp32 -> bf16 hi/lo for all 4 weight tensors
// ---------------------------------------------------------------------------
#define NQKV4  (3 * DIM_ * DIM_ / 4)
#define NPROJ4 (DIM_ * DIM_ / 4)
#define NFC14  (HID_ * DIM_ / 4)
#define NFC24  (DIM_ * HID_ / 4)

__global__ void conv_split_all(const float4* __restrict__ Wq, const float4* __restrict__ Wp,
                               const float4* __restrict__ W1, const float4* __restrict__ W2,
                               uint2* __restrict__ Qh, uint2* __restrict__ Ql,
                               uint2* __restrict__ Ph, uint2* __restrict__ Pl,
                               uint2* __restrict__ F1h, uint2* __restrict__ F1l,
                               uint2* __restrict__ F2h, uint2* __restrict__ F2l) {
    int i = blockIdx.x * blockDim.x + threadIdx.x;
    const float4* src; uint2 *hi, *lo; int j;
    if (i < NQKV4)                               { src = Wq; hi = Qh;  lo = Ql;  j = i; }
    else if ((j = i - NQKV4) < NPROJ4)           { src = Wp; hi = Ph;  lo = Pl; }
    else if ((j = i - NQKV4 - NPROJ4) < NFC14)   { src = W1; hi = F1h; lo = F1l; }
    else { j = i - NQKV4 - NPROJ4 - NFC14; if (j >= NFC24) return;
           src = W2; hi = F2h; lo = F2l; }
    float4 v = src[j];
    uint2 h, l;
    split_pair(v.x, v.y, h.x, l.x);
    split_pair(v.z, v.w, h.y, l.y);
    hi[j] = h; lo[j] = l;
}

// ---------------------------------------------------------------------------
// LayerNorm: one block per row, 256 threads, outputs bf16 hi/lo
// ---------------------------------------------------------------------------
__global__ void ln_kernel(const float* __restrict__ x, const float* __restrict__ g,
                          const float* __restrict__ b,
                          __nv_bfloat16* __restrict__ hi, __nv_bfloat16* __restrict__ lo) {
    __shared__ float red[2][8];
    int row = blockIdx.x, tid = threadIdx.x;
    float4 v = ((const float4*)(x + (size_t)row * DIM_))[tid];
    float s  = v.x + v.y + v.z + v.w;
    float sq = v.x*v.x + v.y*v.y + v.z*v.z + v.w*v.w;
    #pragma unroll
    for (int o = 16; o > 0; o >>= 1) {
        s  += __shfl_xor_sync(0xffffffffu, s,  o);
        sq += __shfl_xor_sync(0xffffffffu, sq, o);
    }
    int wid = tid >> 5, lid = tid & 31;
    if (lid == 0) { red[0][wid] = s; red[1][wid] = sq; }
    __syncthreads();
    s = 0.f; sq = 0.f;
    #pragma unroll
    for (int i = 0; i < 8; i++) { s += red[0][i]; sq += red[1][i]; }
    float mean = s * (1.0f / DIM_);
    float var  = sq * (1.0f / DIM_) - mean * mean;
    float rstd = rsqrtf(var + 1e-5f);
    float4 gg = ((const float4*)g)[tid];
    float4 bb = ((const float4*)b)[tid];
    float o0 = (v.x - mean) * rstd * gg.x + bb.x;
    float o1 = (v.y - mean) * rstd * gg.y + bb.y;
    float o2 = (v.z - mean) * rstd * gg.z + bb.z;
    float o3 = (v.w - mean) * rstd * gg.w + bb.w;
    uint2 h, l;
    split_pair(o0, o1, h.x, l.x);
    split_pair(o2, o3, h.y, l.y);
    size_t off = (size_t)row * DIM_ + tid * 4;
    *(uint2*)(hi + off) = h;
    *(uint2*)(lo + off) = l;
}

// ---------------------------------------------------------------------------
// bf16-split GEMM via mma.sync: C[M,N] = A[M,K] @ B[N,K]^T + bias (+ epilogue)
//   D = Ah*Bh + Ah*Bl + Al*Bh  (fp32 accum)
//   EPI 0: fp32 C = D + bias
//   EPI 1: gelu(D + bias) -> bf16 hi/lo
//   EPI 2: fp32 C = D + bias + res
// 128x128 tile, BK=32, 256 threads (8 warps as 2Mx4N, warp tile 64x32),
// cp.async double buffer. OCCUPANCY 2 (2 CTAs/SM): 2 x 80KB smem = 160KB.
// ---------------------------------------------------------------------------
#define ROWB   80
#define ARRB   10240      // 128 * 80
#define STAGEB 40960      // 4 arrays

template <int EPI>
__global__ void __launch_bounds__(256, 2)
gemm_mma(const __nv_bfloat16* __restrict__ Ahi, const __nv_bfloat16* __restrict__ Alo,
         const __nv_bfloat16* __restrict__ Bhi, const __nv_bfloat16* __restrict__ Blo,
         const float* __restrict__ bias, const float* __restrict__ res,
         float* __restrict__ Cf,
         __nv_bfloat16* __restrict__ Chi, __nv_bfloat16* __restrict__ Clo,
         int M, int N, int K) {
    extern __shared__ char smem[];
    const uint32_t sb = smem_u32(smem);
    const int tid = threadIdx.x, wid = tid >> 5, lane = tid & 31;
    const int warpM = wid & 1, warpN = wid >> 1;     // 2 x 4 warps

    const size_t aoff = (size_t)blockIdx.y * 128 * K;
    const size_t boff = (size_t)blockIdx.x * 128 * K;
    const __nv_bfloat16* srcs[4] = {Ahi + aoff, Alo + aoff, Bhi + boff, Blo + boff};

    // per-thread ldmatrix offsets
    const int mat = lane >> 3, l = lane & 7;
    const uint32_t a_off = (uint32_t)((warpM * 64 + (mat & 1) * 8 + l) * ROWB + (mat >> 1) * 16);
    const uint32_t b_off = (uint32_t)((warpN * 32 + (mat >> 1) * 8 + l) * ROWB + (mat & 1) * 16);

    float acc[4][4][4];
    #pragma unroll
    for (int mi = 0; mi < 4; mi++)
        #pragma unroll
        for (int ni = 0; ni < 4; ni++)
            #pragma unroll
            for (int q = 0; q < 4; q++) acc[mi][ni][q] = 0.f;

    const int NC = K >> 5;

    auto fill = [&](int buf, int c) {
        #pragma unroll
        for (int arr = 0; arr < 4; arr++) {
            const __nv_bfloat16* s = srcs[arr];
            #pragma unroll
            for (int q = 0; q < 2; q++) {
                int idx = tid + q * 256;             // 0..511
                int row = idx >> 2, ch = idx & 3;
                cp16(sb + buf * STAGEB + arr * ARRB + row * ROWB + ch * 16,
                     s + (size_t)row * K + c * 32 + ch * 8);
            }
        }
        CP_COMMIT();
    };

    fill(0, 0);
    for (int c = 0; c < NC; c++) {
        const int buf = c & 1;
        if (c + 1 < NC) fill(buf ^ 1, c + 1); else CP_COMMIT();
        CP_WAIT1();
        __syncthreads();

        const uint32_t As  = sb + buf * STAGEB;
        const uint32_t Als = As + ARRB;
        const uint32_t Bs  = As + 2 * ARRB;
        const uint32_t Bls = As + 3 * ARRB;

        #pragma unroll
        for (int ks = 0; ks < 2; ks++) {
            uint32_t ah[4][4], bh[4][2], bl[4][2], t0[4], t1[4];
            #pragma unroll
            for (int mi = 0; mi < 4; mi++)
                LDSM4(ah[mi], As + a_off + mi * (16 * ROWB) + ks * 32);
            LDSM4(t0, Bs + b_off + ks * 32);
            LDSM4(t1, Bs + b_off + 16 * ROWB + ks * 32);
            bh[0][0]=t0[0]; bh[0][1]=t0[1]; bh[1][0]=t0[2]; bh[1][1]=t0[3];
            bh[2][0]=t1[0]; bh[2][1]=t1[1]; bh[3][0]=t1[2]; bh[3][1]=t1[3];
            LDSM4(t0, Bls + b_off + ks * 32);
            LDSM4(t1, Bls + b_off + 16 * ROWB + ks * 32);
            bl[0][0]=t0[0]; bl[0][1]=t0[1]; bl[1][0]=t0[2]; bl[1][1]=t0[3];
            bl[2][0]=t1[0]; bl[2][1]=t1[1]; bl[3][0]=t1[2]; bl[3][1]=t1[3];

            #pragma unroll
            for (int mi = 0; mi < 4; mi++)
                #pragma unroll
                for (int ni = 0; ni < 4; ni++) {
                    MMA_BF16(acc[mi][ni], ah[mi], bh[ni]);
                    MMA_BF16(acc[mi][ni], ah[mi], bl[ni]);
                }
            uint32_t al[4][4];
            #pragma unroll
            for (int mi = 0; mi < 4; mi++)
                LDSM4(al[mi], Als + a_off + mi * (16 * ROWB) + ks * 32);
            #pragma unroll
            for (int mi = 0; mi < 4; mi++)
                #pragma unroll
                for (int ni = 0; ni < 4; ni++)
                    MMA_BF16(acc[mi][ni], al[mi], bh[ni]);
        }
        __syncthreads();
    }

    // epilogue
    const int r0 = blockIdx.y * 128 + warpM * 64 + (lane >> 2);
    const int cb = blockIdx.x * 128 + warpN * 32 + 2 * (lane & 3);
    float bv[4][2];
    #pragma unroll
    for (int ni = 0; ni < 4; ni++) {
        bv[ni][0] = __ldg(bias + cb + ni * 8);
        bv[ni][1] = __ldg(bias + cb + ni * 8 + 1);
    }
    #pragma unroll
    for (int mi = 0; mi < 4; mi++) {
        #pragma unroll
        for (int ni = 0; ni < 4; ni++) {
            int row = r0 + mi * 16;
            int col = cb + ni * 8;
            float v0 = acc[mi][ni][0] + bv[ni][0];
            float v1 = acc[mi][ni][1] + bv[ni][1];
            float v2 = acc[mi][ni][2] + bv[ni][0];
            float v3 = acc[mi][ni][3] + bv[ni][1];
            size_t o0 = (size_t)row * N + col;
            size_t o1 = (size_t)(row + 8) * N + col;
            if (EPI == 1) {
                v0 = 0.5f * v0 * (1.0f + erff(v0 * 0.70710678118654752f));
                v1 = 0.5f * v1 * (1.0f + erff(v1 * 0.70710678118654752f));
                v2 = 0.5f * v2 * (1.0f + erff(v2 * 0.70710678118654752f));
                v3 = 0.5f * v3 * (1.0f + erff(v3 * 0.70710678118654752f));
                uint32_t hp, lp;
                split_pair(v0, v1, hp, lp);
                *(uint32_t*)(Chi + o0) = hp; *(uint32_t*)(Clo + o0) = lp;
                split_pair(v2, v3, hp, lp);
                *(uint32_t*)(Chi + o1) = hp; *(uint32_t*)(Clo + o1) = lp;
            } else {
                if (EPI == 2) {
                    float2 ra = *(const float2*)(res + o0);
                    float2 rb = *(const float2*)(res + o1);
                    v0 += ra.x; v1 += ra.y; v2 += rb.x; v3 += rb.y;
                }
                *(float2*)(Cf + o0) = make_float2(v0, v1);
                *(float2*)(Cf + o1) = make_float2(v2, v3);
            }
        }
    }
}

// ---------------------------------------------------------------------------
// Flash attention, fp32 (proven), output split to bf16 hi/lo
// ---------------------------------------------------------------------------
__global__ void __launch_bounds__(256, 1)
attn_kernel(const float* __restrict__ QKV,
            __nv_bfloat16* __restrict__ Ohi, __nv_bfloat16* __restrict__ Olo) {
    extern __shared__ float sm[];
    float* Qs = sm;
    float* Kt = sm + 8192;
    float* Vs = sm + 16384;
    float* Ps = sm + 24576;
    const int bb = blockIdx.x >> 4, h = blockIdx.x & 15;
    const int q0 = blockIdx.y * 128;
    const int tid = threadIdx.x;
    const int tx = tid & 15, ty = tid >> 4;
    const size_t base = (size_t)bb * 1024 * 3072 + (size_t)h * 64;
    const float scale = 0.125f;

    for (int i = tid; i < 2048; i += 256) {
        int r = i >> 4, c4 = (i & 15) << 2;
        float4 v = *(const float4*)(QKV + base + (size_t)(q0 + r) * 3072 + c4);
        v.x *= scale; v.y *= scale; v.z *= scale; v.w *= scale;
        *(float4*)&Qs[r * 64 + c4] = v;
    }

    float m_i[8], l_i[8], o[8][4];
    #pragma unroll
    for (int i = 0; i < 8; i++) {
        m_i[i] = -1e30f; l_i[i] = 0.f;
        #pragma unroll
        for (int j = 0; j < 4; j++) o[i][j] = 0.f;
    }

    for (int kt = 0; kt < 8; kt++) {
        __syncthreads();
        for (int i = tid; i < 2048; i += 256) {
            int r = i >> 4, c4 = (i & 15) << 2;
            const float* src = QKV + base + (size_t)(kt * 128 + r) * 3072;
            float4 kv = *(const float4*)(src + 1024 + c4);
            Kt[(c4 + 0) * 128 + r] = kv.x;
            Kt[(c4 + 1) * 128 + r] = kv.y;
            Kt[(c4 + 2) * 128 + r] = kv.z;
            Kt[(c4 + 3) * 128 + r] = kv.w;
            *(float4*)&Vs[r * 64 + c4] = *(const float4*)(src + 2048 + c4);
        }
        __syncthreads();

        float s[8][8];
        #pragma unroll
        for (int i = 0; i < 8; i++)
            #pragma unroll
            for (int j = 0; j < 8; j++) s[i][j] = 0.f;
        for (int kk = 0; kk < 64; kk++) {
            float a[8];
            #pragma unroll
            for (int i = 0; i < 8; i++) a[i] = Qs[(ty * 8 + i) * 64 + kk];
            float4 b0 = *(float4*)&Kt[kk * 128 + tx * 8];
            float4 b1 = *(float4*)&Kt[kk * 128 + tx * 8 + 4];
            float b[8] = {b0.x,b0.y,b0.z,b0.w,b1.x,b1.y,b1.z,b1.w};
            #pragma unroll
            for (int i = 0; i < 8; i++)
                #pragma unroll
                for (int j = 0; j < 8; j++)
                    s[i][j] += a[i] * b[j];
        }

        #pragma unroll
        for (int i = 0; i < 8; i++) {
            float mx = s[i][0];
            #pragma unroll
            for (int j = 1; j < 8; j++) mx = fmaxf(mx, s[i][j]);
            #pragma unroll
            for (int off = 8; off > 0; off >>= 1)
                mx = fmaxf(mx, __shfl_xor_sync(0xffffffffu, mx, off));
            float m_new = fmaxf(m_i[i], mx);
            float corr = __expf(m_i[i] - m_new);
            float p[8], rs = 0.f;
            #pragma unroll
            for (int j = 0; j < 8; j++) { p[j] = __expf(s[i][j] - m_new); rs += p[j]; }
            #pragma unroll
            for (int off = 8; off > 0; off >>= 1)
                rs += __shfl_xor_sync(0xffffffffu, rs, off);
            l_i[i] = l_i[i] * corr + rs;
            m_i[i] = m_new;
            #pragma unroll
            for (int j = 0; j < 4; j++) o[i][j] *= corr;
            *(float4*)&Ps[(ty * 8 + i) * 128 + tx * 8]     = make_float4(p[0],p[1],p[2],p[3]);
            *(float4*)&Ps[(ty * 8 + i) * 128 + tx * 8 + 4] = make_float4(p[4],p[5],p[6],p[7]);
        }
        __syncwarp();

        for (int kk = 0; kk < 128; kk++) {
            float4 vv = *(float4*)&Vs[kk * 64 + tx * 4];
            #pragma unroll
            for (int i = 0; i < 8; i++) {
                float pp = Ps[(ty * 8 + i) * 128 + kk];
                o[i][0] += pp * vv.x; o[i][1] += pp * vv.y;
                o[i][2] += pp * vv.z; o[i][3] += pp * vv.w;
            }
        }
    }

    #pragma unroll
    for (int i = 0; i < 8; i++) {
        float inv = 1.0f / l_i[i];
        int tok = bb * 1024 + q0 + ty * 8 + i;
        float v0 = o[i][0]*inv, v1 = o[i][1]*inv, v2 = o[i][2]*inv, v3 = o[i][3]*inv;
        uint2 hp, lp;
        split_pair(v0, v1, hp.x, lp.x);
        split_pair(v2, v3, hp.y, lp.y);
        size_t off = (size_t)tok * 1024 + h * 64 + tx * 4;
        *(uint2*)(Ohi + off) = hp;
        *(uint2*)(Olo + off) = lp;
    }
}

// ---------------------------------------------------------------------------
extern "C" void kernel_launch(void* const* d_in, const int* in_sizes, int n_in,
                              void* d_out, int out_size) {
    const float* x      = (const float*)d_in[0];
    const float* ln1_g  = (const float*)d_in[1];
    const float* ln1_b  = (const float*)d_in[2];
    const float* qkv_w  = (const float*)d_in[3];
    const float* qkv_b  = (const float*)d_in[4];
    const float* proj_w = (const float*)d_in[5];
    const float* proj_b = (const float*)d_in[6];
    const float* ln2_g  = (const float*)d_in[7];
    const float* ln2_b  = (const float*)d_in[8];
    const float* fc1_w  = (const float*)d_in[9];
    const float* fc1_b  = (const float*)d_in[10];
    const float* fc2_w  = (const float*)d_in[11];
    const float* fc2_b  = (const float*)d_in[12];
    float* out = (float*)d_out;

    float *QKV, *X1;
    __nv_bfloat16 *Hh,*Hl,*Oh,*Ol,*Gh,*Gl,*Wqh,*Wql,*Wph,*Wpl,*W1h,*W1l,*W2h,*W2l;
    cudaGetSymbolAddress((void**)&QKV, g_QKV);
    cudaGetSymbolAddress((void**)&X1,  g_X1);
    cudaGetSymbolAddress((void**)&Hh,  g_Hhi);  cudaGetSymbolAddress((void**)&Hl, g_Hlo);
    cudaGetSymbolAddress((void**)&Oh,  g_Ohi);  cudaGetSymbolAddress((void**)&Ol, g_Olo);
    cudaGetSymbolAddress((void**)&Gh,  g_Ghi);  cudaGetSymbolAddress((void**)&Gl, g_Glo);
    cudaGetSymbolAddress((void**)&Wqh, g_Wqkv_h); cudaGetSymbolAddress((void**)&Wql, g_Wqkv_l);
    cudaGetSymbolAddress((void**)&Wph, g_Wproj_h); cudaGetSymbolAddress((void**)&Wpl, g_Wproj_l);
    cudaGetSymbolAddress((void**)&W1h, g_Wfc1_h); cudaGetSymbolAddress((void**)&W1l, g_Wfc1_l);
    cudaGetSymbolAddress((void**)&W2h, g_Wfc2_h); cudaGetSymbolAddress((void**)&W2l, g_Wfc2_l);

    const int GSM = 2 * STAGEB;   // 81920
    cudaFuncSetAttribute(gemm_mma<0>, cudaFuncAttributeMaxDynamicSharedMemorySize, GSM);
    cudaFuncSetAttribute(gemm_mma<1>, cudaFuncAttributeMaxDynamicSharedMemorySize, GSM);
    cudaFuncSetAttribute(gemm_mma<2>, cudaFuncAttributeMaxDynamicSharedMemorySize, GSM);
    cudaFuncSetAttribute(attn_kernel, cudaFuncAttributeMaxDynamicSharedMemorySize, 163840);

    // weight splits (single launch)
    {
        int total = NQKV4 + NPROJ4 + NFC14 + NFC24;
        conv_split_all<<<(total + 255) / 256, 256>>>(
            (const float4*)qkv_w, (const float4*)proj_w,
            (const float4*)fc1_w, (const float4*)fc2_w,
            (uint2*)Wqh, (uint2*)Wql, (uint2*)Wph, (uint2*)Wpl,
            (uint2*)W1h, (uint2*)W1l, (uint2*)W2h, (uint2*)W2l);
    }

    // 1) LN1 -> H (bf16 hi/lo)
    ln_kernel<<<TOK, 256>>>(x, ln1_g, ln1_b, Hh, Hl);
    // 2) QKV = H @ qkv_w^T + b  (fp32 out)
    gemm_mma<0><<<dim3(3072/128, TOK/128), 256, GSM>>>(Hh, Hl, Wqh, Wql, qkv_b,
                                                       nullptr, QKV, nullptr, nullptr,
                                                       TOK, 3072, DIM_);
    // 3) attention -> O (bf16 hi/lo)
    attn_kernel<<<dim3(64, 8), 256, 163840>>>(QKV, Oh, Ol);
    // 4) X1 = x + O @ proj_w^T + b
    gemm_mma<2><<<dim3(DIM_/128, TOK/128), 256, GSM>>>(Oh, Ol, Wph, Wpl, proj_b,
                                                       x, X1, nullptr, nullptr,
                                                       TOK, DIM_, DIM_);
    // 5) LN2 -> H
    ln_kernel<<<TOK, 256>>>(X1, ln2_g, ln2_b, Hh, Hl);
    // 6) G = gelu(H @ fc1_w^T + b) (bf16 hi/lo out)
    gemm_mma<1><<<dim3(HID_/128, TOK/128), 256, GSM>>>(Hh, Hl, W1h, W1l, fc1_b,
                                                       nullptr, nullptr, Gh, Gl,
                                                       TOK, HID_, DIM_);
    // 7) out = X1 + G @ fc2_w^T + b
    gemm_mma<2><<<dim3(DIM_/128, TOK/128), 256, GSM>>>(Gh, Gl, W2h, W2l, fc2_b,
                                                       X1, out, nullptr, nullptr,
                                                       TOK, DIM_, HID_);
}

// round 9
// speedup vs baseline: 3.2686x; 1.3437x over previous
#include <cuda_runtime.h>
#include <cuda_bf16.h>
#include <math.h>
#include <stdint.h>

#define TOK   4096
#define DIM_  1024
#define HID_  4096

// ---------------- scratch (__device__ globals; no allocations) -------------
__device__ float          g_QKV [(size_t)TOK * 3 * DIM_];
__device__ float          g_X1  [(size_t)TOK * DIM_];
__device__ __nv_bfloat16  g_Hhi [(size_t)TOK * DIM_];
__device__ __nv_bfloat16  g_Hlo [(size_t)TOK * DIM_];
__device__ __nv_bfloat16  g_Ohi [(size_t)TOK * DIM_];
__device__ __nv_bfloat16  g_Olo [(size_t)TOK * DIM_];
__device__ __nv_bfloat16  g_Ghi [(size_t)TOK * HID_];
__device__ __nv_bfloat16  g_Glo [(size_t)TOK * HID_];
__device__ __nv_bfloat16  g_Wqkv_h[(size_t)3 * DIM_ * DIM_];
__device__ __nv_bfloat16  g_Wqkv_l[(size_t)3 * DIM_ * DIM_];
__device__ __nv_bfloat16  g_Wproj_h[(size_t)DIM_ * DIM_];
__device__ __nv_bfloat16  g_Wproj_l[(size_t)DIM_ * DIM_];
__device__ __nv_bfloat16  g_Wfc1_h[(size_t)HID_ * DIM_];
__device__ __nv_bfloat16  g_Wfc1_l[(size_t)HID_ * DIM_];
__device__ __nv_bfloat16  g_Wfc2_h[(size_t)DIM_ * HID_];
__device__ __nv_bfloat16  g_Wfc2_l[(size_t)DIM_ * HID_];

// ---------------- helpers ---------------------------------------------------
__device__ __forceinline__ uint32_t smem_u32(const void* p) {
    uint32_t a;
    asm("{ .reg .u64 t; cvta.to.shared.u64 t, %1; cvt.u32.u64 %0, t; }"
        : "=r"(a) : "l"(p));
    return a;
}
__device__ __forceinline__ void cp16(uint32_t dst, const void* src) {
    asm volatile("cp.async.cg.shared.global [%0], [%1], 16;" :: "r"(dst), "l"(src));
}
#define CP_COMMIT() asm volatile("cp.async.commit_group;" ::: "memory")
#define CP_WAIT1()  asm volatile("cp.async.wait_group 1;"  ::: "memory")

#define LDSM4(r, addr) \
    asm volatile("ldmatrix.sync.aligned.m8n8.x4.shared.b16 {%0,%1,%2,%3}, [%4];" \
        : "=r"((r)[0]), "=r"((r)[1]), "=r"((r)[2]), "=r"((r)[3]) : "r"(addr))

#define MMA_BF16(c, a, b) \
    asm volatile("mma.sync.aligned.m16n8k16.row.col.f32.bf16.bf16.f32 " \
        "{%0,%1,%2,%3}, {%4,%5,%6,%7}, {%8,%9}, {%0,%1,%2,%3};" \
        : "+f"((c)[0]), "+f"((c)[1]), "+f"((c)[2]), "+f"((c)[3]) \
        : "r"((a)[0]), "r"((a)[1]), "r"((a)[2]), "r"((a)[3]), \
          "r"((b)[0]), "r"((b)[1]))

// split a fp32 pair into packed bf16x2 hi/lo words
__device__ __forceinline__ void split_pair(float v0, float v1, uint32_t& hp, uint32_t& lp) {
    __nv_bfloat162 h2 = __floats2bfloat162_rn(v0, v1);
    float h0 = __bfloat162float(h2.x), h1 = __bfloat162float(h2.y);
    __nv_bfloat162 l2 = __floats2bfloat162_rn(v0 - h0, v1 - h1);
    hp = *reinterpret_cast<uint32_t*>(&h2);
    lp = *reinterpret_cast<uint32_t*>(&l2);
}

// ---------------------------------------------------------------------------
// combined weight split kernel
// ---------------------------------------------------------------------------
#define NQKV4  (3 * DIM_ * DIM_ / 4)
#define NPROJ4 (DIM_ * DIM_ / 4)
#define NFC14  (HID_ * DIM_ / 4)
#define NFC24  (DIM_ * HID_ / 4)

__global__ void conv_split_all(const float4* __restrict__ Wq, const float4* __restrict__ Wp,
                               const float4* __restrict__ W1, const float4* __restrict__ W2,
                               uint2* __restrict__ Qh, uint2* __restrict__ Ql,
                               uint2* __restrict__ Ph, uint2* __restrict__ Pl,
                               uint2* __restrict__ F1h, uint2* __restrict__ F1l,
                               uint2* __restrict__ F2h, uint2* __restrict__ F2l) {
    int i = blockIdx.x * blockDim.x + threadIdx.x;
    const float4* src; uint2 *hi, *lo; int j;
    if (i < NQKV4)                               { src = Wq; hi = Qh;  lo = Ql;  j = i; }
    else if ((j = i - NQKV4) < NPROJ4)           { src = Wp; hi = Ph;  lo = Pl; }
    else if ((j = i - NQKV4 - NPROJ4) < NFC14)   { src = W1; hi = F1h; lo = F1l; }
    else { j = i - NQKV4 - NPROJ4 - NFC14; if (j >= NFC24) return;
           src = W2; hi = F2h; lo = F2l; }
    float4 v = src[j];
    uint2 h, l;
    split_pair(v.x, v.y, h.x, l.x);
    split_pair(v.z, v.w, h.y, l.y);
    hi[j] = h; lo[j] = l;
}

// ---------------------------------------------------------------------------
// LayerNorm: one block per row, 256 threads, outputs bf16 hi/lo
// ---------------------------------------------------------------------------
__global__ void ln_kernel(const float* __restrict__ x, const float* __restrict__ g,
                          const float* __restrict__ b,
                          __nv_bfloat16* __restrict__ hi, __nv_bfloat16* __restrict__ lo) {
    __shared__ float red[2][8];
    int row = blockIdx.x, tid = threadIdx.x;
    float4 v = ((const float4*)(x + (size_t)row * DIM_))[tid];
    float s  = v.x + v.y + v.z + v.w;
    float sq = v.x*v.x + v.y*v.y + v.z*v.z + v.w*v.w;
    #pragma unroll
    for (int o = 16; o > 0; o >>= 1) {
        s  += __shfl_xor_sync(0xffffffffu, s,  o);
        sq += __shfl_xor_sync(0xffffffffu, sq, o);
    }
    int wid = tid >> 5, lid = tid & 31;
    if (lid == 0) { red[0][wid] = s; red[1][wid] = sq; }
    __syncthreads();
    s = 0.f; sq = 0.f;
    #pragma unroll
    for (int i = 0; i < 8; i++) { s += red[0][i]; sq += red[1][i]; }
    float mean = s * (1.0f / DIM_);
    float var  = sq * (1.0f / DIM_) - mean * mean;
    float rstd = rsqrtf(var + 1e-5f);
    float4 gg = ((const float4*)g)[tid];
    float4 bb = ((const float4*)b)[tid];
    float o0 = (v.x - mean) * rstd * gg.x + bb.x;
    float o1 = (v.y - mean) * rstd * gg.y + bb.y;
    float o2 = (v.z - mean) * rstd * gg.z + bb.z;
    float o3 = (v.w - mean) * rstd * gg.w + bb.w;
    uint2 h, l;
    split_pair(o0, o1, h.x, l.x);
    split_pair(o2, o3, h.y, l.y);
    size_t off = (size_t)row * DIM_ + tid * 4;
    *(uint2*)(hi + off) = h;
    *(uint2*)(lo + off) = l;
}

// ---------------------------------------------------------------------------
// bf16-split GEMM via mma.sync (proven round-8 version, 2 CTAs/SM)
// ---------------------------------------------------------------------------
#define ROWB   80
#define ARRB   10240
#define STAGEB 40960

template <int EPI>
__global__ void __launch_bounds__(256, 2)
gemm_mma(const __nv_bfloat16* __restrict__ Ahi, const __nv_bfloat16* __restrict__ Alo,
         const __nv_bfloat16* __restrict__ Bhi, const __nv_bfloat16* __restrict__ Blo,
         const float* __restrict__ bias, const float* __restrict__ res,
         float* __restrict__ Cf,
         __nv_bfloat16* __restrict__ Chi, __nv_bfloat16* __restrict__ Clo,
         int M, int N, int K) {
    extern __shared__ char smem[];
    const uint32_t sb = smem_u32(smem);
    const int tid = threadIdx.x, wid = tid >> 5, lane = tid & 31;
    const int warpM = wid & 1, warpN = wid >> 1;

    const size_t aoff = (size_t)blockIdx.y * 128 * K;
    const size_t boff = (size_t)blockIdx.x * 128 * K;
    const __nv_bfloat16* srcs[4] = {Ahi + aoff, Alo + aoff, Bhi + boff, Blo + boff};

    const int mat = lane >> 3, l = lane & 7;
    const uint32_t a_off = (uint32_t)((warpM * 64 + (mat & 1) * 8 + l) * ROWB + (mat >> 1) * 16);
    const uint32_t b_off = (uint32_t)((warpN * 32 + (mat >> 1) * 8 + l) * ROWB + (mat & 1) * 16);

    float acc[4][4][4];
    #pragma unroll
    for (int mi = 0; mi < 4; mi++)
        #pragma unroll
        for (int ni = 0; ni < 4; ni++)
            #pragma unroll
            for (int q = 0; q < 4; q++) acc[mi][ni][q] = 0.f;

    const int NC = K >> 5;

    auto fill = [&](int buf, int c) {
        #pragma unroll
        for (int arr = 0; arr < 4; arr++) {
            const __nv_bfloat16* s = srcs[arr];
            #pragma unroll
            for (int q = 0; q < 2; q++) {
                int idx = tid + q * 256;
                int row = idx >> 2, ch = idx & 3;
                cp16(sb + buf * STAGEB + arr * ARRB + row * ROWB + ch * 16,
                     s + (size_t)row * K + c * 32 + ch * 8);
            }
        }
        CP_COMMIT();
    };

    fill(0, 0);
    for (int c = 0; c < NC; c++) {
        const int buf = c & 1;
        if (c + 1 < NC) fill(buf ^ 1, c + 1); else CP_COMMIT();
        CP_WAIT1();
        __syncthreads();

        const uint32_t As  = sb + buf * STAGEB;
        const uint32_t Als = As + ARRB;
        const uint32_t Bs  = As + 2 * ARRB;
        const uint32_t Bls = As + 3 * ARRB;

        #pragma unroll
        for (int ks = 0; ks < 2; ks++) {
            uint32_t ah[4][4], bh[4][2], bl[4][2], t0[4], t1[4];
            #pragma unroll
            for (int mi = 0; mi < 4; mi++)
                LDSM4(ah[mi], As + a_off + mi * (16 * ROWB) + ks * 32);
            LDSM4(t0, Bs + b_off + ks * 32);
            LDSM4(t1, Bs + b_off + 16 * ROWB + ks * 32);
            bh[0][0]=t0[0]; bh[0][1]=t0[1]; bh[1][0]=t0[2]; bh[1][1]=t0[3];
            bh[2][0]=t1[0]; bh[2][1]=t1[1]; bh[3][0]=t1[2]; bh[3][1]=t1[3];
            LDSM4(t0, Bls + b_off + ks * 32);
            LDSM4(t1, Bls + b_off + 16 * ROWB + ks * 32);
            bl[0][0]=t0[0]; bl[0][1]=t0[1]; bl[1][0]=t0[2]; bl[1][1]=t0[3];
            bl[2][0]=t1[0]; bl[2][1]=t1[1]; bl[3][0]=t1[2]; bl[3][1]=t1[3];

            #pragma unroll
            for (int mi = 0; mi < 4; mi++)
                #pragma unroll
                for (int ni = 0; ni < 4; ni++) {
                    MMA_BF16(acc[mi][ni], ah[mi], bh[ni]);
                    MMA_BF16(acc[mi][ni], ah[mi], bl[ni]);
                }
            uint32_t al[4][4];
            #pragma unroll
            for (int mi = 0; mi < 4; mi++)
                LDSM4(al[mi], Als + a_off + mi * (16 * ROWB) + ks * 32);
            #pragma unroll
            for (int mi = 0; mi < 4; mi++)
                #pragma unroll
                for (int ni = 0; ni < 4; ni++)
                    MMA_BF16(acc[mi][ni], al[mi], bh[ni]);
        }
        __syncthreads();
    }

    const int r0 = blockIdx.y * 128 + warpM * 64 + (lane >> 2);
    const int cb = blockIdx.x * 128 + warpN * 32 + 2 * (lane & 3);
    float bv[4][2];
    #pragma unroll
    for (int ni = 0; ni < 4; ni++) {
        bv[ni][0] = __ldg(bias + cb + ni * 8);
        bv[ni][1] = __ldg(bias + cb + ni * 8 + 1);
    }
    #pragma unroll
    for (int mi = 0; mi < 4; mi++) {
        #pragma unroll
        for (int ni = 0; ni < 4; ni++) {
            int row = r0 + mi * 16;
            int col = cb + ni * 8;
            float v0 = acc[mi][ni][0] + bv[ni][0];
            float v1 = acc[mi][ni][1] + bv[ni][1];
            float v2 = acc[mi][ni][2] + bv[ni][0];
            float v3 = acc[mi][ni][3] + bv[ni][1];
            size_t o0 = (size_t)row * N + col;
            size_t o1 = (size_t)(row + 8) * N + col;
            if (EPI == 1) {
                v0 = 0.5f * v0 * (1.0f + erff(v0 * 0.70710678118654752f));
                v1 = 0.5f * v1 * (1.0f + erff(v1 * 0.70710678118654752f));
                v2 = 0.5f * v2 * (1.0f + erff(v2 * 0.70710678118654752f));
                v3 = 0.5f * v3 * (1.0f + erff(v3 * 0.70710678118654752f));
                uint32_t hp, lp;
                split_pair(v0, v1, hp, lp);
                *(uint32_t*)(Chi + o0) = hp; *(uint32_t*)(Clo + o0) = lp;
                split_pair(v2, v3, hp, lp);
                *(uint32_t*)(Chi + o1) = hp; *(uint32_t*)(Clo + o1) = lp;
            } else {
                if (EPI == 2) {
                    float2 ra = *(const float2*)(res + o0);
                    float2 rb = *(const float2*)(res + o1);
                    v0 += ra.x; v1 += ra.y; v2 += rb.x; v3 += rb.y;
                }
                *(float2*)(Cf + o0) = make_float2(v0, v1);
                *(float2*)(Cf + o1) = make_float2(v2, v3);
            }
        }
    }
}

// ---------------------------------------------------------------------------
// Flash attention via mma.sync, bf16 3-term split for QK and PV.
// Grid (64 bh, 8 q-tiles), 256 threads, warp grid 4M x 2N.
//   S tile 128x128: warp tile 32x64.  O tile 128x64: warp tile 32x32.
// Smem layout (bytes):
//   Qh/Ql: 128 rows x 64 bf16, stride 144   -> 18432 each
//   Kh/Kl: 128 rows x 64 bf16, stride 144   -> 18432 each
//   Vth/Vtl: 64 rows(dim) x 128 bf16, 272   -> 17408 each
//   Ph/Pl: 128 rows x 128 bf16, stride 272  -> 34816 each
//   rmax[128][2], rsum[128][2], mS[128], lS[128]
// ---------------------------------------------------------------------------
#define ROWQ 144
#define ROWV 272
#define ROWP 272
#define OQH 0
#define OQL 18432
#define OKH 36864
#define OKL 55296
#define OVH 73728
#define OVL 91136
#define OPH 108544
#define OPL 143360
#define ORMAX 178176
#define ORSUM 179200
#define OMS   180224
#define OLS   180736
#define ATTN_SMEM 181248

__global__ void __launch_bounds__(256, 1)
attn_mma(const float* __restrict__ QKV,
         __nv_bfloat16* __restrict__ Ohi, __nv_bfloat16* __restrict__ Olo) {
    extern __shared__ char sm[];
    const uint32_t sb = smem_u32(sm);
    const int bb = blockIdx.x >> 4, h = blockIdx.x & 15;
    const int q0 = blockIdx.y * 128;
    const int tid = threadIdx.x, wid = tid >> 5, lane = tid & 31;
    const int warpM = wid & 3, warpN = wid >> 2;
    const int mat = lane >> 3, l8 = lane & 7;
    const int quad = lane >> 2, qlane = lane & 3;
    const size_t base = (size_t)bb * 1024 * 3072 + (size_t)h * 64;

    float* rmaxp = (float*)(sm + ORMAX);
    float* rsump = (float*)(sm + ORSUM);
    float* mSp   = (float*)(sm + OMS);
    float* lSp   = (float*)(sm + OLS);

    if (tid < 128) { mSp[tid] = -1e30f; lSp[tid] = 0.f; }

    // load Q tile (scaled), split to bf16 hi/lo
    for (int i = tid; i < 2048; i += 256) {
        int r = i >> 4, c4 = (i & 15) << 2;
        float4 v = *(const float4*)(QKV + base + (size_t)(q0 + r) * 3072 + c4);
        v.x *= 0.125f; v.y *= 0.125f; v.z *= 0.125f; v.w *= 0.125f;
        uint2 hp, lp;
        split_pair(v.x, v.y, hp.x, lp.x);
        split_pair(v.z, v.w, hp.y, lp.y);
        *(uint2*)(sm + OQH + r * ROWQ + c4 * 2) = hp;
        *(uint2*)(sm + OQL + r * ROWQ + c4 * 2) = lp;
    }

    // ldmatrix offsets
    const uint32_t aq_off = (uint32_t)((warpM * 32 + (mat & 1) * 8 + l8) * ROWQ + (mat >> 1) * 16);
    const uint32_t bk_off = (uint32_t)((warpN * 64 + (mat >> 1) * 8 + l8) * ROWQ + (mat & 1) * 16);
    const uint32_t ap_off = (uint32_t)((warpM * 32 + (mat & 1) * 8 + l8) * ROWP + (mat >> 1) * 16);
    const uint32_t bv_off = (uint32_t)((warpN * 32 + (mat >> 1) * 8 + l8) * ROWV + (mat & 1) * 16);

    float Oacc[2][4][4];
    #pragma unroll
    for (int mi = 0; mi < 2; mi++)
        #pragma unroll
        for (int ni = 0; ni < 4; ni++)
            #pragma unroll
            for (int q = 0; q < 4; q++) Oacc[mi][ni][q] = 0.f;

    for (int kt = 0; kt < 8; kt++) {
        __syncthreads();
        // load K tile + V tile (transposed), split to bf16 hi/lo
        for (int i = tid; i < 2048; i += 256) {
            int r = i >> 4, c4 = (i & 15) << 2;
            const float* src = QKV + base + (size_t)(kt * 128 + r) * 3072;
            float4 kv = *(const float4*)(src + 1024 + c4);
            uint2 hp, lp;
            split_pair(kv.x, kv.y, hp.x, lp.x);
            split_pair(kv.z, kv.w, hp.y, lp.y);
            *(uint2*)(sm + OKH + r * ROWQ + c4 * 2) = hp;
            *(uint2*)(sm + OKL + r * ROWQ + c4 * 2) = lp;
            float4 vv = *(const float4*)(src + 2048 + c4);
            #pragma unroll
            for (int j = 0; j < 4; j++) {
                float f = (&vv.x)[j];
                __nv_bfloat16 hb = __float2bfloat16_rn(f);
                __nv_bfloat16 lb = __float2bfloat16_rn(f - __bfloat162float(hb));
                *(__nv_bfloat16*)(sm + OVH + (c4 + j) * ROWV + r * 2) = hb;
                *(__nv_bfloat16*)(sm + OVL + (c4 + j) * ROWV + r * 2) = lb;
            }
        }
        __syncthreads();

        // ---- S = Q K^T (3-term split) ----
        float S[2][8][4];
        #pragma unroll
        for (int mi = 0; mi < 2; mi++)
            #pragma unroll
            for (int ni = 0; ni < 8; ni++)
                #pragma unroll
                for (int q = 0; q < 4; q++) S[mi][ni][q] = 0.f;

        #pragma unroll
        for (int ks = 0; ks < 4; ks++) {
            uint32_t ah[2][4], al[2][4], bh[8][2], bl[8][2], t0[4];
            #pragma unroll
            for (int mi = 0; mi < 2; mi++) {
                LDSM4(ah[mi], sb + OQH + aq_off + mi * (16 * ROWQ) + ks * 32);
                LDSM4(al[mi], sb + OQL + aq_off + mi * (16 * ROWQ) + ks * 32);
            }
            #pragma unroll
            for (int nq = 0; nq < 4; nq++) {
                LDSM4(t0, sb + OKH + bk_off + nq * (16 * ROWQ) + ks * 32);
                bh[2*nq][0] = t0[0]; bh[2*nq][1] = t0[1];
                bh[2*nq+1][0] = t0[2]; bh[2*nq+1][1] = t0[3];
                LDSM4(t0, sb + OKL + bk_off + nq * (16 * ROWQ) + ks * 32);
                bl[2*nq][0] = t0[0]; bl[2*nq][1] = t0[1];
                bl[2*nq+1][0] = t0[2]; bl[2*nq+1][1] = t0[3];
            }
            #pragma unroll
            for (int mi = 0; mi < 2; mi++)
                #pragma unroll
                for (int ni = 0; ni < 8; ni++) {
                    MMA_BF16(S[mi][ni], ah[mi], bh[ni]);
                    MMA_BF16(S[mi][ni], ah[mi], bl[ni]);
                    MMA_BF16(S[mi][ni], al[mi], bh[ni]);
                }
        }

        // ---- online softmax ----
        float lmax[2][2];
        #pragma unroll
        for (int mi = 0; mi < 2; mi++)
            #pragma unroll
            for (int qh = 0; qh < 2; qh++) {
                float m = S[mi][0][qh*2];
                #pragma unroll
                for (int ni = 0; ni < 8; ni++) {
                    m = fmaxf(m, S[mi][ni][qh*2]);
                    m = fmaxf(m, S[mi][ni][qh*2+1]);
                }
                m = fmaxf(m, __shfl_xor_sync(0xffffffffu, m, 1));
                m = fmaxf(m, __shfl_xor_sync(0xffffffffu, m, 2));
                lmax[mi][qh] = m;
            }
        if (qlane == 0) {
            #pragma unroll
            for (int mi = 0; mi < 2; mi++)
                #pragma unroll
                for (int qh = 0; qh < 2; qh++) {
                    int row = warpM * 32 + mi * 16 + quad + 8 * qh;
                    rmaxp[row * 2 + warpN] = lmax[mi][qh];
                }
        }
        __syncthreads();

        float corr[2][2], mnew[2][2], lsum[2][2];
        #pragma unroll
        for (int mi = 0; mi < 2; mi++)
            #pragma unroll
            for (int qh = 0; qh < 2; qh++) {
                int row = warpM * 32 + mi * 16 + quad + 8 * qh;
                float mn = fmaxf(rmaxp[row * 2], rmaxp[row * 2 + 1]);
                float mold = mSp[row];
                mn = fmaxf(mold, mn);
                mnew[mi][qh] = mn;
                corr[mi][qh] = __expf(mold - mn);
                float s = 0.f;
                #pragma unroll
                for (int ni = 0; ni < 8; ni++) {
                    float p0 = __expf(S[mi][ni][qh*2]   - mn);
                    float p1 = __expf(S[mi][ni][qh*2+1] - mn);
                    s += p0 + p1;
                    uint32_t hp, lp;
                    split_pair(p0, p1, hp, lp);
                    int col = warpN * 64 + ni * 8 + 2 * qlane;
                    *(uint32_t*)(sm + OPH + row * ROWP + col * 2) = hp;
                    *(uint32_t*)(sm + OPL + row * ROWP + col * 2) = lp;
                }
                s += __shfl_xor_sync(0xffffffffu, s, 1);
                s += __shfl_xor_sync(0xffffffffu, s, 2);
                lsum[mi][qh] = s;
            }
        if (qlane == 0) {
            #pragma unroll
            for (int mi = 0; mi < 2; mi++)
                #pragma unroll
                for (int qh = 0; qh < 2; qh++) {
                    int row = warpM * 32 + mi * 16 + quad + 8 * qh;
                    rsump[row * 2 + warpN] = lsum[mi][qh];
                }
        }
        __syncthreads();
        if (warpN == 0 && qlane == 0) {
            #pragma unroll
            for (int mi = 0; mi < 2; mi++)
                #pragma unroll
                for (int qh = 0; qh < 2; qh++) {
                    int row = warpM * 32 + mi * 16 + quad + 8 * qh;
                    lSp[row] = lSp[row] * corr[mi][qh] + rsump[row * 2] + rsump[row * 2 + 1];
                    mSp[row] = mnew[mi][qh];
                }
        }
        // rescale O
        #pragma unroll
        for (int mi = 0; mi < 2; mi++)
            #pragma unroll
            for (int ni = 0; ni < 4; ni++)
                #pragma unroll
                for (int q = 0; q < 4; q++)
                    Oacc[mi][ni][q] *= corr[mi][q >> 1];

        // ---- O += P V (3-term split) ----
        #pragma unroll
        for (int ks = 0; ks < 8; ks++) {
            uint32_t ph[2][4], pl[2][4], vh[4][2], vl[4][2], t0[4], t1[4];
            #pragma unroll
            for (int mi = 0; mi < 2; mi++) {
                LDSM4(ph[mi], sb + OPH + ap_off + mi * (16 * ROWP) + ks * 32);
                LDSM4(pl[mi], sb + OPL + ap_off + mi * (16 * ROWP) + ks * 32);
            }
            LDSM4(t0, sb + OVH + bv_off + ks * 32);
            LDSM4(t1, sb + OVH + bv_off + 16 * ROWV + ks * 32);
            vh[0][0]=t0[0]; vh[0][1]=t0[1]; vh[1][0]=t0[2]; vh[1][1]=t0[3];
            vh[2][0]=t1[0]; vh[2][1]=t1[1]; vh[3][0]=t1[2]; vh[3][1]=t1[3];
            LDSM4(t0, sb + OVL + bv_off + ks * 32);
            LDSM4(t1, sb + OVL + bv_off + 16 * ROWV + ks * 32);
            vl[0][0]=t0[0]; vl[0][1]=t0[1]; vl[1][0]=t0[2]; vl[1][1]=t0[3];
            vl[2][0]=t1[0]; vl[2][1]=t1[1]; vl[3][0]=t1[2]; vl[3][1]=t1[3];
            #pragma unroll
            for (int mi = 0; mi < 2; mi++)
                #pragma unroll
                for (int ni = 0; ni < 4; ni++) {
                    MMA_BF16(Oacc[mi][ni], ph[mi], vh[ni]);
                    MMA_BF16(Oacc[mi][ni], ph[mi], vl[ni]);
                    MMA_BF16(Oacc[mi][ni], pl[mi], vh[ni]);
                }
        }
    }

    __syncthreads();
    // write out: O /= l, split to bf16 hi/lo
    #pragma unroll
    for (int mi = 0; mi < 2; mi++)
        #pragma unroll
        for (int qh = 0; qh < 2; qh++) {
            int row = warpM * 32 + mi * 16 + quad + 8 * qh;
            float inv = 1.0f / lSp[row];
            int tok = bb * 1024 + q0 + row;
            #pragma unroll
            for (int ni = 0; ni < 4; ni++) {
                int col = warpN * 32 + ni * 8 + 2 * qlane;
                float v0 = Oacc[mi][ni][qh*2]   * inv;
                float v1 = Oacc[mi][ni][qh*2+1] * inv;
                uint32_t hp, lp;
                split_pair(v0, v1, hp, lp);
                size_t off = (size_t)tok * 1024 + h * 64 + col;
                *(uint32_t*)(Ohi + off) = hp;
                *(uint32_t*)(Olo + off) = lp;
            }
        }
}

// ---------------------------------------------------------------------------
extern "C" void kernel_launch(void* const* d_in, const int* in_sizes, int n_in,
                              void* d_out, int out_size) {
    const float* x      = (const float*)d_in[0];
    const float* ln1_g  = (const float*)d_in[1];
    const float* ln1_b  = (const float*)d_in[2];
    const float* qkv_w  = (const float*)d_in[3];
    const float* qkv_b  = (const float*)d_in[4];
    const float* proj_w = (const float*)d_in[5];
    const float* proj_b = (const float*)d_in[6];
    const float* ln2_g  = (const float*)d_in[7];
    const float* ln2_b  = (const float*)d_in[8];
    const float* fc1_w  = (const float*)d_in[9];
    const float* fc1_b  = (const float*)d_in[10];
    const float* fc2_w  = (const float*)d_in[11];
    const float* fc2_b  = (const float*)d_in[12];
    float* out = (float*)d_out;

    float *QKV, *X1;
    __nv_bfloat16 *Hh,*Hl,*Oh,*Ol,*Gh,*Gl,*Wqh,*Wql,*Wph,*Wpl,*W1h,*W1l,*W2h,*W2l;
    cudaGetSymbolAddress((void**)&QKV, g_QKV);
    cudaGetSymbolAddress((void**)&X1,  g_X1);
    cudaGetSymbolAddress((void**)&Hh,  g_Hhi);  cudaGetSymbolAddress((void**)&Hl, g_Hlo);
    cudaGetSymbolAddress((void**)&Oh,  g_Ohi);  cudaGetSymbolAddress((void**)&Ol, g_Olo);
    cudaGetSymbolAddress((void**)&Gh,  g_Ghi);  cudaGetSymbolAddress((void**)&Gl, g_Glo);
    cudaGetSymbolAddress((void**)&Wqh, g_Wqkv_h); cudaGetSymbolAddress((void**)&Wql, g_Wqkv_l);
    cudaGetSymbolAddress((void**)&Wph, g_Wproj_h); cudaGetSymbolAddress((void**)&Wpl, g_Wproj_l);
    cudaGetSymbolAddress((void**)&W1h, g_Wfc1_h); cudaGetSymbolAddress((void**)&W1l, g_Wfc1_l);
    cudaGetSymbolAddress((void**)&W2h, g_Wfc2_h); cudaGetSymbolAddress((void**)&W2l, g_Wfc2_l);

    const int GSM = 2 * STAGEB;
    cudaFuncSetAttribute(gemm_mma<0>, cudaFuncAttributeMaxDynamicSharedMemorySize, GSM);
    cudaFuncSetAttribute(gemm_mma<1>, cudaFuncAttributeMaxDynamicSharedMemorySize, GSM);
    cudaFuncSetAttribute(gemm_mma<2>, cudaFuncAttributeMaxDynamicSharedMemorySize, GSM);
    cudaFuncSetAttribute(attn_mma, cudaFuncAttributeMaxDynamicSharedMemorySize, ATTN_SMEM);

    {
        int total = NQKV4 + NPROJ4 + NFC14 + NFC24;
        conv_split_all<<<(total + 255) / 256, 256>>>(
            (const float4*)qkv_w, (const float4*)proj_w,
            (const float4*)fc1_w, (const float4*)fc2_w,
            (uint2*)Wqh, (uint2*)Wql, (uint2*)Wph, (uint2*)Wpl,
            (uint2*)W1h, (uint2*)W1l, (uint2*)W2h, (uint2*)W2l);
    }

    ln_kernel<<<TOK, 256>>>(x, ln1_g, ln1_b, Hh, Hl);
    gemm_mma<0><<<dim3(3072/128, TOK/128), 256, GSM>>>(Hh, Hl, Wqh, Wql, qkv_b,
                                                       nullptr, QKV, nullptr, nullptr,
                                                       TOK, 3072, DIM_);
    attn_mma<<<dim3(64, 8), 256, ATTN_SMEM>>>(QKV, Oh, Ol);
    gemm_mma<2><<<dim3(DIM_/128, TOK/128), 256, GSM>>>(Oh, Ol, Wph, Wpl, proj_b,
                                                       x, X1, nullptr, nullptr,
                                                       TOK, DIM_, DIM_);
    ln_kernel<<<TOK, 256>>>(X1, ln2_g, ln2_b, Hh, Hl);
    gemm_mma<1><<<dim3(HID_/128, TOK/128), 256, GSM>>>(Hh, Hl, W1h, W1l, fc1_b,
                                                       nullptr, nullptr, Gh, Gl,
                                                       TOK, HID_, DIM_);
    gemm_mma<2><<<dim3(DIM_/128, TOK/128), 256, GSM>>>(Gh, Gl, W2h, W2l, fc2_b,
                                                       X1, out, nullptr, nullptr,
                                                       TOK, DIM_, HID_);
}

// round 11
// speedup vs baseline: 4.1489x; 1.2693x over previous
#include <cuda_runtime.h>
#include <cuda_bf16.h>
#include <cuda_fp16.h>
#include <math.h>
#include <stdint.h>

#define TOK   4096
#define DIM_  1024
#define HID_  4096

// ---------------- scratch (__device__ globals; no allocations) -------------
__device__ float   g_QKV [(size_t)TOK * 3 * DIM_];
__device__ float   g_X1  [(size_t)TOK * DIM_];
__device__ __half  g_Hhi [(size_t)TOK * DIM_];
__device__ __half  g_Hlo [(size_t)TOK * DIM_];
__device__ __half  g_Ohi [(size_t)TOK * DIM_];
__device__ __half  g_Olo [(size_t)TOK * DIM_];
__device__ __half  g_Ghi [(size_t)TOK * HID_];
__device__ __half  g_Glo [(size_t)TOK * HID_];
__device__ __half  g_Wqkv[(size_t)3 * DIM_ * DIM_];
__device__ __half  g_Wproj[(size_t)DIM_ * DIM_];
__device__ __half  g_Wfc1[(size_t)HID_ * DIM_];
__device__ __half  g_Wfc2[(size_t)DIM_ * HID_];

// ---------------- helpers ---------------------------------------------------
__device__ __forceinline__ uint32_t smem_u32(const void* p) {
    uint32_t a;
    asm("{ .reg .u64 t; cvta.to.shared.u64 t, %1; cvt.u32.u64 %0, t; }"
        : "=r"(a) : "l"(p));
    return a;
}
__device__ __forceinline__ void cp16(uint32_t dst, const void* src) {
    asm volatile("cp.async.cg.shared.global [%0], [%1], 16;" :: "r"(dst), "l"(src));
}
#define CP_COMMIT() asm volatile("cp.async.commit_group;" ::: "memory")
#define CP_WAIT1()  asm volatile("cp.async.wait_group 1;"  ::: "memory")

#define LDSM4(r, addr) \
    asm volatile("ldmatrix.sync.aligned.m8n8.x4.shared.b16 {%0,%1,%2,%3}, [%4];" \
        : "=r"((r)[0]), "=r"((r)[1]), "=r"((r)[2]), "=r"((r)[3]) : "r"(addr))

#define MMA_BF16(c, a, b) \
    asm volatile("mma.sync.aligned.m16n8k16.row.col.f32.bf16.bf16.f32 " \
        "{%0,%1,%2,%3}, {%4,%5,%6,%7}, {%8,%9}, {%0,%1,%2,%3};" \
        : "+f"((c)[0]), "+f"((c)[1]), "+f"((c)[2]), "+f"((c)[3]) \
        : "r"((a)[0]), "r"((a)[1]), "r"((a)[2]), "r"((a)[3]), \
          "r"((b)[0]), "r"((b)[1]))

#define MMA_F16(c, a, b) \
    asm volatile("mma.sync.aligned.m16n8k16.row.col.f32.f16.f16.f32 " \
        "{%0,%1,%2,%3}, {%4,%5,%6,%7}, {%8,%9}, {%0,%1,%2,%3};" \
        : "+f"((c)[0]), "+f"((c)[1]), "+f"((c)[2]), "+f"((c)[3]) \
        : "r"((a)[0]), "r"((a)[1]), "r"((a)[2]), "r"((a)[3]), \
          "r"((b)[0]), "r"((b)[1]))

// split fp32 pair -> packed bf16x2 hi/lo
__device__ __forceinline__ void split_pair(float v0, float v1, uint32_t& hp, uint32_t& lp) {
    __nv_bfloat162 h2 = __floats2bfloat162_rn(v0, v1);
    float h0 = __bfloat162float(h2.x), h1 = __bfloat162float(h2.y);
    __nv_bfloat162 l2 = __floats2bfloat162_rn(v0 - h0, v1 - h1);
    hp = *reinterpret_cast<uint32_t*>(&h2);
    lp = *reinterpret_cast<uint32_t*>(&l2);
}
// split fp32 pair -> packed fp16x2 hi/lo
__device__ __forceinline__ void split_pair_h(float v0, float v1, uint32_t& hp, uint32_t& lp) {
    __half2 h2 = __floats2half2_rn(v0, v1);
    float h0 = __low2float(h2), h1 = __high2float(h2);
    __half2 l2 = __floats2half2_rn(v0 - h0, v1 - h1);
    hp = *reinterpret_cast<uint32_t*>(&h2);
    lp = *reinterpret_cast<uint32_t*>(&l2);
}

// ---------------------------------------------------------------------------
// weight conversion: fp32 -> single fp16 (all 4 weights, one launch)
// ---------------------------------------------------------------------------
#define NQKV4  (3 * DIM_ * DIM_ / 4)
#define NPROJ4 (DIM_ * DIM_ / 4)
#define NFC14  (HID_ * DIM_ / 4)
#define NFC24  (DIM_ * HID_ / 4)

__global__ void conv_all(const float4* __restrict__ Wq, const float4* __restrict__ Wp,
                         const float4* __restrict__ W1, const float4* __restrict__ W2,
                         uint2* __restrict__ Q, uint2* __restrict__ P,
                         uint2* __restrict__ F1, uint2* __restrict__ F2) {
    int i = blockIdx.x * blockDim.x + threadIdx.x;
    const float4* src; uint2* dst; int j;
    if (i < NQKV4)                               { src = Wq; dst = Q;  j = i; }
    else if ((j = i - NQKV4) < NPROJ4)           { src = Wp; dst = P; }
    else if ((j = i - NQKV4 - NPROJ4) < NFC14)   { src = W1; dst = F1; }
    else { j = i - NQKV4 - NPROJ4 - NFC14; if (j >= NFC24) return;
           src = W2; dst = F2; }
    float4 v = src[j];
    __half2 a = __floats2half2_rn(v.x, v.y);
    __half2 b = __floats2half2_rn(v.z, v.w);
    uint2 o;
    o.x = *reinterpret_cast<uint32_t*>(&a);
    o.y = *reinterpret_cast<uint32_t*>(&b);
    dst[j] = o;
}

// ---------------------------------------------------------------------------
// LayerNorm: one block per row, 256 threads, outputs fp16 hi/lo
// ---------------------------------------------------------------------------
__global__ void ln_kernel(const float* __restrict__ x, const float* __restrict__ g,
                          const float* __restrict__ b,
                          __half* __restrict__ hi, __half* __restrict__ lo) {
    __shared__ float red[2][8];
    int row = blockIdx.x, tid = threadIdx.x;
    float4 v = ((const float4*)(x + (size_t)row * DIM_))[tid];
    float s  = v.x + v.y + v.z + v.w;
    float sq = v.x*v.x + v.y*v.y + v.z*v.z + v.w*v.w;
    #pragma unroll
    for (int o = 16; o > 0; o >>= 1) {
        s  += __shfl_xor_sync(0xffffffffu, s,  o);
        sq += __shfl_xor_sync(0xffffffffu, sq, o);
    }
    int wid = tid >> 5, lid = tid & 31;
    if (lid == 0) { red[0][wid] = s; red[1][wid] = sq; }
    __syncthreads();
    s = 0.f; sq = 0.f;
    #pragma unroll
    for (int i = 0; i < 8; i++) { s += red[0][i]; sq += red[1][i]; }
    float mean = s * (1.0f / DIM_);
    float var  = sq * (1.0f / DIM_) - mean * mean;
    float rstd = rsqrtf(var + 1e-5f);
    float4 gg = ((const float4*)g)[tid];
    float4 bb = ((const float4*)b)[tid];
    float o0 = (v.x - mean) * rstd * gg.x + bb.x;
    float o1 = (v.y - mean) * rstd * gg.y + bb.y;
    float o2 = (v.z - mean) * rstd * gg.z + bb.z;
    float o3 = (v.w - mean) * rstd * gg.w + bb.w;
    uint2 h, l;
    split_pair_h(o0, o1, h.x, l.x);
    split_pair_h(o2, o3, h.y, l.y);
    size_t off = (size_t)row * DIM_ + tid * 4;
    *(uint2*)(hi + off) = h;
    *(uint2*)(lo + off) = l;
}

// ---------------------------------------------------------------------------
// fp16 asymmetric-split GEMM via mma.sync:
//   C[M,N] = (Ah + Al)[M,K] @ B_fp16[N,K]^T + bias (+ epilogue)
//   D = Ah*B + Al*B  (2 terms; fp32 accum)
// 128x128 tile, BK=32, 256 threads (2Mx4N warps), cp.async double buffer,
// 3 smem arrays/stage (Ah, Al, B), 2 CTAs/SM.
// ---------------------------------------------------------------------------
#define ROWB   80
#define ARRB   10240      // 128 * 80
#define STAGEB 30720      // 3 arrays

template <int EPI>
__global__ void __launch_bounds__(256, 2)
gemm_mma(const __half* __restrict__ Ahi, const __half* __restrict__ Alo,
         const __half* __restrict__ B,
         const float* __restrict__ bias, const float* __restrict__ res,
         float* __restrict__ Cf,
         __half* __restrict__ Chi, __half* __restrict__ Clo,
         int M, int N, int K) {
    extern __shared__ char smem[];
    const uint32_t sb = smem_u32(smem);
    const int tid = threadIdx.x, wid = tid >> 5, lane = tid & 31;
    const int warpM = wid & 1, warpN = wid >> 1;

    const size_t aoff = (size_t)blockIdx.y * 128 * K;
    const size_t boff = (size_t)blockIdx.x * 128 * K;
    const __half* srcs[3] = {Ahi + aoff, Alo + aoff, B + boff};

    const int mat = lane >> 3, l = lane & 7;
    const uint32_t a_off = (uint32_t)((warpM * 64 + (mat & 1) * 8 + l) * ROWB + (mat >> 1) * 16);
    const uint32_t b_off = (uint32_t)((warpN * 32 + (mat >> 1) * 8 + l) * ROWB + (mat & 1) * 16);

    float acc[4][4][4];
    #pragma unroll
    for (int mi = 0; mi < 4; mi++)
        #pragma unroll
        for (int ni = 0; ni < 4; ni++)
            #pragma unroll
            for (int q = 0; q < 4; q++) acc[mi][ni][q] = 0.f;

    const int NC = K >> 5;

    auto fill = [&](int buf, int c) {
        #pragma unroll
        for (int arr = 0; arr < 3; arr++) {
            const __half* s = srcs[arr];
            #pragma unroll
            for (int q = 0; q < 2; q++) {
                int idx = tid + q * 256;
                int row = idx >> 2, ch = idx & 3;
                cp16(sb + buf * STAGEB + arr * ARRB + row * ROWB + ch * 16,
                     s + (size_t)row * K + c * 32 + ch * 8);
            }
        }
        CP_COMMIT();
    };

    fill(0, 0);
    for (int c = 0; c < NC; c++) {
        const int buf = c & 1;
        if (c + 1 < NC) fill(buf ^ 1, c + 1); else CP_COMMIT();
        CP_WAIT1();
        __syncthreads();

        const uint32_t As  = sb + buf * STAGEB;
        const uint32_t Als = As + ARRB;
        const uint32_t Bs  = As + 2 * ARRB;

        #pragma unroll
        for (int ks = 0; ks < 2; ks++) {
            uint32_t ah[4][4], al[4][4], bh[4][2], t0[4], t1[4];
            #pragma unroll
            for (int mi = 0; mi < 4; mi++) {
                LDSM4(ah[mi], As  + a_off + mi * (16 * ROWB) + ks * 32);
                LDSM4(al[mi], Als + a_off + mi * (16 * ROWB) + ks * 32);
            }
            LDSM4(t0, Bs + b_off + ks * 32);
            LDSM4(t1, Bs + b_off + 16 * ROWB + ks * 32);
            bh[0][0]=t0[0]; bh[0][1]=t0[1]; bh[1][0]=t0[2]; bh[1][1]=t0[3];
            bh[2][0]=t1[0]; bh[2][1]=t1[1]; bh[3][0]=t1[2]; bh[3][1]=t1[3];

            // two separated sweeps: 16 independent accs between same-acc reuses
            #pragma unroll
            for (int mi = 0; mi < 4; mi++)
                #pragma unroll
                for (int ni = 0; ni < 4; ni++)
                    MMA_F16(acc[mi][ni], ah[mi], bh[ni]);
            #pragma unroll
            for (int mi = 0; mi < 4; mi++)
                #pragma unroll
                for (int ni = 0; ni < 4; ni++)
                    MMA_F16(acc[mi][ni], al[mi], bh[ni]);
        }
        __syncthreads();
    }

    const int r0 = blockIdx.y * 128 + warpM * 64 + (lane >> 2);
    const int cb = blockIdx.x * 128 + warpN * 32 + 2 * (lane & 3);
    float bv[4][2];
    #pragma unroll
    for (int ni = 0; ni < 4; ni++) {
        bv[ni][0] = __ldg(bias + cb + ni * 8);
        bv[ni][1] = __ldg(bias + cb + ni * 8 + 1);
    }
    #pragma unroll
    for (int mi = 0; mi < 4; mi++) {
        #pragma unroll
        for (int ni = 0; ni < 4; ni++) {
            int row = r0 + mi * 16;
            int col = cb + ni * 8;
            float v0 = acc[mi][ni][0] + bv[ni][0];
            float v1 = acc[mi][ni][1] + bv[ni][1];
            float v2 = acc[mi][ni][2] + bv[ni][0];
            float v3 = acc[mi][ni][3] + bv[ni][1];
            size_t o0 = (size_t)row * N + col;
            size_t o1 = (size_t)(row + 8) * N + col;
            if (EPI == 1) {
                v0 = 0.5f * v0 * (1.0f + erff(v0 * 0.70710678118654752f));
                v1 = 0.5f * v1 * (1.0f + erff(v1 * 0.70710678118654752f));
                v2 = 0.5f * v2 * (1.0f + erff(v2 * 0.70710678118654752f));
                v3 = 0.5f * v3 * (1.0f + erff(v3 * 0.70710678118654752f));
                uint32_t hp, lp;
                split_pair_h(v0, v1, hp, lp);
                *(uint32_t*)(Chi + o0) = hp; *(uint32_t*)(Clo + o0) = lp;
                split_pair_h(v2, v3, hp, lp);
                *(uint32_t*)(Chi + o1) = hp; *(uint32_t*)(Clo + o1) = lp;
            } else {
                if (EPI == 2) {
                    float2 ra = *(const float2*)(res + o0);
                    float2 rb = *(const float2*)(res + o1);
                    v0 += ra.x; v1 += ra.y; v2 += rb.x; v3 += rb.y;
                }
                *(float2*)(Cf + o0) = make_float2(v0, v1);
                *(float2*)(Cf + o1) = make_float2(v2, v3);
            }
        }
    }
}

// ---------------------------------------------------------------------------
// Flash attention via mma.sync, bf16 3-term split (proven round-9 version);
// output now split to fp16 hi/lo for the fp16 proj GEMM.
// ---------------------------------------------------------------------------
#define ROWQ 144
#define ROWV 272
#define ROWP 272
#define OQH 0
#define OQL 18432
#define OKH 36864
#define OKL 55296
#define OVH 73728
#define OVL 91136
#define OPH 108544
#define OPL 143360
#define ORMAX 178176
#define ORSUM 179200
#define OMS   180224
#define OLS   180736
#define ATTN_SMEM 181248

__global__ void __launch_bounds__(256, 1)
attn_mma(const float* __restrict__ QKV,
         __half* __restrict__ Ohi, __half* __restrict__ Olo) {
    extern __shared__ char sm[];
    const uint32_t sb = smem_u32(sm);
    const int bb = blockIdx.x >> 4, h = blockIdx.x & 15;
    const int q0 = blockIdx.y * 128;
    const int tid = threadIdx.x, wid = tid >> 5, lane = tid & 31;
    const int warpM = wid & 3, warpN = wid >> 2;
    const int mat = lane >> 3, l8 = lane & 7;
    const int quad = lane >> 2, qlane = lane & 3;
    const size_t base = (size_t)bb * 1024 * 3072 + (size_t)h * 64;

    float* rmaxp = (float*)(sm + ORMAX);
    float* rsump = (float*)(sm + ORSUM);
    float* mSp   = (float*)(sm + OMS);
    float* lSp   = (float*)(sm + OLS);

    if (tid < 128) { mSp[tid] = -1e30f; lSp[tid] = 0.f; }

    for (int i = tid; i < 2048; i += 256) {
        int r = i >> 4, c4 = (i & 15) << 2;
        float4 v = *(const float4*)(QKV + base + (size_t)(q0 + r) * 3072 + c4);
        v.x *= 0.125f; v.y *= 0.125f; v.z *= 0.125f; v.w *= 0.125f;
        uint2 hp, lp;
        split_pair(v.x, v.y, hp.x, lp.x);
        split_pair(v.z, v.w, hp.y, lp.y);
        *(uint2*)(sm + OQH + r * ROWQ + c4 * 2) = hp;
        *(uint2*)(sm + OQL + r * ROWQ + c4 * 2) = lp;
    }

    const uint32_t aq_off = (uint32_t)((warpM * 32 + (mat & 1) * 8 + l8) * ROWQ + (mat >> 1) * 16);
    const uint32_t bk_off = (uint32_t)((warpN * 64 + (mat >> 1) * 8 + l8) * ROWQ + (mat & 1) * 16);
    const uint32_t ap_off = (uint32_t)((warpM * 32 + (mat & 1) * 8 + l8) * ROWP + (mat >> 1) * 16);
    const uint32_t bv_off = (uint32_t)((warpN * 32 + (mat >> 1) * 8 + l8) * ROWV + (mat & 1) * 16);

    float Oacc[2][4][4];
    #pragma unroll
    for (int mi = 0; mi < 2; mi++)
        #pragma unroll
        for (int ni = 0; ni < 4; ni++)
            #pragma unroll
            for (int q = 0; q < 4; q++) Oacc[mi][ni][q] = 0.f;

    for (int kt = 0; kt < 8; kt++) {
        __syncthreads();
        for (int i = tid; i < 2048; i += 256) {
            int r = i >> 4, c4 = (i & 15) << 2;
            const float* src = QKV + base + (size_t)(kt * 128 + r) * 3072;
            float4 kv = *(const float4*)(src + 1024 + c4);
            uint2 hp, lp;
            split_pair(kv.x, kv.y, hp.x, lp.x);
            split_pair(kv.z, kv.w, hp.y, lp.y);
            *(uint2*)(sm + OKH + r * ROWQ + c4 * 2) = hp;
            *(uint2*)(sm + OKL + r * ROWQ + c4 * 2) = lp;
            float4 vv = *(const float4*)(src + 2048 + c4);
            #pragma unroll
            for (int j = 0; j < 4; j++) {
                float f = (&vv.x)[j];
                __nv_bfloat16 hb = __float2bfloat16_rn(f);
                __nv_bfloat16 lb = __float2bfloat16_rn(f - __bfloat162float(hb));
                *(__nv_bfloat16*)(sm + OVH + (c4 + j) * ROWV + r * 2) = hb;
                *(__nv_bfloat16*)(sm + OVL + (c4 + j) * ROWV + r * 2) = lb;
            }
        }
        __syncthreads();

        // ---- S = Q K^T (3-term split, separated sweeps) ----
        float S[2][8][4];
        #pragma unroll
        for (int mi = 0; mi < 2; mi++)
            #pragma unroll
            for (int ni = 0; ni < 8; ni++)
                #pragma unroll
                for (int q = 0; q < 4; q++) S[mi][ni][q] = 0.f;

        #pragma unroll
        for (int ks = 0; ks < 4; ks++) {
            uint32_t ah[2][4], al[2][4], bh[8][2], bl[8][2], t0[4];
            #pragma unroll
            for (int mi = 0; mi < 2; mi++) {
                LDSM4(ah[mi], sb + OQH + aq_off + mi * (16 * ROWQ) + ks * 32);
                LDSM4(al[mi], sb + OQL + aq_off + mi * (16 * ROWQ) + ks * 32);
            }
            #pragma unroll
            for (int nq = 0; nq < 4; nq++) {
                LDSM4(t0, sb + OKH + bk_off + nq * (16 * ROWQ) + ks * 32);
                bh[2*nq][0] = t0[0]; bh[2*nq][1] = t0[1];
                bh[2*nq+1][0] = t0[2]; bh[2*nq+1][1] = t0[3];
                LDSM4(t0, sb + OKL + bk_off + nq * (16 * ROWQ) + ks * 32);
                bl[2*nq][0] = t0[0]; bl[2*nq][1] = t0[1];
                bl[2*nq+1][0] = t0[2]; bl[2*nq+1][1] = t0[3];
            }
            #pragma unroll
            for (int mi = 0; mi < 2; mi++)
                #pragma unroll
                for (int ni = 0; ni < 8; ni++)
                    MMA_BF16(S[mi][ni], ah[mi], bh[ni]);
            #pragma unroll
            for (int mi = 0; mi < 2; mi++)
                #pragma unroll
                for (int ni = 0; ni < 8; ni++)
                    MMA_BF16(S[mi][ni], ah[mi], bl[ni]);
            #pragma unroll
            for (int mi = 0; mi < 2; mi++)
                #pragma unroll
                for (int ni = 0; ni < 8; ni++)
                    MMA_BF16(S[mi][ni], al[mi], bh[ni]);
        }

        // ---- online softmax ----
        float lmax[2][2];
        #pragma unroll
        for (int mi = 0; mi < 2; mi++)
            #pragma unroll
            for (int qh = 0; qh < 2; qh++) {
                float m = S[mi][0][qh*2];
                #pragma unroll
                for (int ni = 0; ni < 8; ni++) {
                    m = fmaxf(m, S[mi][ni][qh*2]);
                    m = fmaxf(m, S[mi][ni][qh*2+1]);
                }
                m = fmaxf(m, __shfl_xor_sync(0xffffffffu, m, 1));
                m = fmaxf(m, __shfl_xor_sync(0xffffffffu, m, 2));
                lmax[mi][qh] = m;
            }
        if (qlane == 0) {
            #pragma unroll
            for (int mi = 0; mi < 2; mi++)
                #pragma unroll
                for (int qh = 0; qh < 2; qh++) {
                    int row = warpM * 32 + mi * 16 + quad + 8 * qh;
                    rmaxp[row * 2 + warpN] = lmax[mi][qh];
                }
        }
        __syncthreads();

        float corr[2][2], mnew[2][2], lsum[2][2];
        #pragma unroll
        for (int mi = 0; mi < 2; mi++)
            #pragma unroll
            for (int qh = 0; qh < 2; qh++) {
                int row = warpM * 32 + mi * 16 + quad + 8 * qh;
                float mn = fmaxf(rmaxp[row * 2], rmaxp[row * 2 + 1]);
                float mold = mSp[row];
                mn = fmaxf(mold, mn);
                mnew[mi][qh] = mn;
                corr[mi][qh] = __expf(mold - mn);
                float s = 0.f;
                #pragma unroll
                for (int ni = 0; ni < 8; ni++) {
                    float p0 = __expf(S[mi][ni][qh*2]   - mn);
                    float p1 = __expf(S[mi][ni][qh*2+1] - mn);
                    s += p0 + p1;
                    uint32_t hp, lp;
                    split_pair(p0, p1, hp, lp);
                    int col = warpN * 64 + ni * 8 + 2 * qlane;
                    *(uint32_t*)(sm + OPH + row * ROWP + col * 2) = hp;
                    *(uint32_t*)(sm + OPL + row * ROWP + col * 2) = lp;
                }
                s += __shfl_xor_sync(0xffffffffu, s, 1);
                s += __shfl_xor_sync(0xffffffffu, s, 2);
                lsum[mi][qh] = s;
            }
        if (qlane == 0) {
            #pragma unroll
            for (int mi = 0; mi < 2; mi++)
                #pragma unroll
                for (int qh = 0; qh < 2; qh++) {
                    int row = warpM * 32 + mi * 16 + quad + 8 * qh;
                    rsump[row * 2 + warpN] = lsum[mi][qh];
                }
        }
        __syncthreads();
        if (warpN == 0 && qlane == 0) {
            #pragma unroll
            for (int mi = 0; mi < 2; mi++)
                #pragma unroll
                for (int qh = 0; qh < 2; qh++) {
                    int row = warpM * 32 + mi * 16 + quad + 8 * qh;
                    lSp[row] = lSp[row] * corr[mi][qh] + rsump[row * 2] + rsump[row * 2 + 1];
                    mSp[row] = mnew[mi][qh];
                }
        }
        #pragma unroll
        for (int mi = 0; mi < 2; mi++)
            #pragma unroll
            for (int ni = 0; ni < 4; ni++)
                #pragma unroll
                for (int q = 0; q < 4; q++)
                    Oacc[mi][ni][q] *= corr[mi][q >> 1];

        // ---- O += P V (3-term split, separated sweeps) ----
        #pragma unroll
        for (int ks = 0; ks < 8; ks++) {
            uint32_t ph[2][4], pl[2][4], vh[4][2], vl[4][2], t0[4], t1[4];
            #pragma unroll
            for (int mi = 0; mi < 2; mi++) {
                LDSM4(ph[mi], sb + OPH + ap_off + mi * (16 * ROWP) + ks * 32);
                LDSM4(pl[mi], sb + OPL + ap_off + mi * (16 * ROWP) + ks * 32);
            }
            LDSM4(t0, sb + OVH + bv_off + ks * 32);
            LDSM4(t1, sb + OVH + bv_off + 16 * ROWV + ks * 32);
            vh[0][0]=t0[0]; vh[0][1]=t0[1]; vh[1][0]=t0[2]; vh[1][1]=t0[3];
            vh[2][0]=t1[0]; vh[2][1]=t1[1]; vh[3][0]=t1[2]; vh[3][1]=t1[3];
            LDSM4(t0, sb + OVL + bv_off + ks * 32);
            LDSM4(t1, sb + OVL + bv_off + 16 * ROWV + ks * 32);
            vl[0][0]=t0[0]; vl[0][1]=t0[1]; vl[1][0]=t0[2]; vl[1][1]=t0[3];
            vl[2][0]=t1[0]; vl[2][1]=t1[1]; vl[3][0]=t1[2]; vl[3][1]=t1[3];
            #pragma unroll
            for (int mi = 0; mi < 2; mi++)
                #pragma unroll
                for (int ni = 0; ni < 4; ni++)
                    MMA_BF16(Oacc[mi][ni], ph[mi], vh[ni]);
            #pragma unroll
            for (int mi = 0; mi < 2; mi++)
                #pragma unroll
                for (int ni = 0; ni < 4; ni++)
                    MMA_BF16(Oacc[mi][ni], ph[mi], vl[ni]);
            #pragma unroll
            for (int mi = 0; mi < 2; mi++)
                #pragma unroll
                for (int ni = 0; ni < 4; ni++)
                    MMA_BF16(Oacc[mi][ni], pl[mi], vh[ni]);
        }
    }

    __syncthreads();
    #pragma unroll
    for (int mi = 0; mi < 2; mi++)
        #pragma unroll
        for (int qh = 0; qh < 2; qh++) {
            int row = warpM * 32 + mi * 16 + quad + 8 * qh;
            float inv = 1.0f / lSp[row];
            int tok = bb * 1024 + q0 + row;
            #pragma unroll
            for (int ni = 0; ni < 4; ni++) {
                int col = warpN * 32 + ni * 8 + 2 * qlane;
                float v0 = Oacc[mi][ni][qh*2]   * inv;
                float v1 = Oacc[mi][ni][qh*2+1] * inv;
                uint32_t hp, lp;
                split_pair_h(v0, v1, hp, lp);
                size_t off = (size_t)tok * 1024 + h * 64 + col;
                *(uint32_t*)(Ohi + off) = hp;
                *(uint32_t*)(Olo + off) = lp;
            }
        }
}

// ---------------------------------------------------------------------------
extern "C" void kernel_launch(void* const* d_in, const int* in_sizes, int n_in,
                              void* d_out, int out_size) {
    const float* x      = (const float*)d_in[0];
    const float* ln1_g  = (const float*)d_in[1];
    const float* ln1_b  = (const float*)d_in[2];
    const float* qkv_w  = (const float*)d_in[3];
    const float* qkv_b  = (const float*)d_in[4];
    const float* proj_w = (const float*)d_in[5];
    const float* proj_b = (const float*)d_in[6];
    const float* ln2_g  = (const float*)d_in[7];
    const float* ln2_b  = (const float*)d_in[8];
    const float* fc1_w  = (const float*)d_in[9];
    const float* fc1_b  = (const float*)d_in[10];
    const float* fc2_w  = (const float*)d_in[11];
    const float* fc2_b  = (const float*)d_in[12];
    float* out = (float*)d_out;

    float *QKV, *X1;
    __half *Hh,*Hl,*Oh,*Ol,*Gh,*Gl,*Wq,*Wp,*W1,*W2;
    cudaGetSymbolAddress((void**)&QKV, g_QKV);
    cudaGetSymbolAddress((void**)&X1,  g_X1);
    cudaGetSymbolAddress((void**)&Hh,  g_Hhi);  cudaGetSymbolAddress((void**)&Hl, g_Hlo);
    cudaGetSymbolAddress((void**)&Oh,  g_Ohi);  cudaGetSymbolAddress((void**)&Ol, g_Olo);
    cudaGetSymbolAddress((void**)&Gh,  g_Ghi);  cudaGetSymbolAddress((void**)&Gl, g_Glo);
    cudaGetSymbolAddress((void**)&Wq,  g_Wqkv);
    cudaGetSymbolAddress((void**)&Wp,  g_Wproj);
    cudaGetSymbolAddress((void**)&W1,  g_Wfc1);
    cudaGetSymbolAddress((void**)&W2,  g_Wfc2);

    const int GSM = 2 * STAGEB;   // 61440
    cudaFuncSetAttribute(gemm_mma<0>, cudaFuncAttributeMaxDynamicSharedMemorySize, GSM);
    cudaFuncSetAttribute(gemm_mma<1>, cudaFuncAttributeMaxDynamicSharedMemorySize, GSM);
    cudaFuncSetAttribute(gemm_mma<2>, cudaFuncAttributeMaxDynamicSharedMemorySize, GSM);
    cudaFuncSetAttribute(attn_mma, cudaFuncAttributeMaxDynamicSharedMemorySize, ATTN_SMEM);

    {
        int total = NQKV4 + NPROJ4 + NFC14 + NFC24;
        conv_all<<<(total + 255) / 256, 256>>>(
            (const float4*)qkv_w, (const float4*)proj_w,
            (const float4*)fc1_w, (const float4*)fc2_w,
            (uint2*)Wq, (uint2*)Wp, (uint2*)W1, (uint2*)W2);
    }

    ln_kernel<<<TOK, 256>>>(x, ln1_g, ln1_b, Hh, Hl);
    gemm_mma<0><<<dim3(3072/128, TOK/128), 256, GSM>>>(Hh, Hl, Wq, qkv_b,
                                                       nullptr, QKV, nullptr, nullptr,
                                                       TOK, 3072, DIM_);
    attn_mma<<<dim3(64, 8), 256, ATTN_SMEM>>>(QKV, Oh, Ol);
    gemm_mma<2><<<dim3(DIM_/128, TOK/128), 256, GSM>>>(Oh, Ol, Wp, proj_b,
                                                       x, X1, nullptr, nullptr,
                                                       TOK, DIM_, DIM_);
    ln_kernel<<<TOK, 256>>>(X1, ln2_g, ln2_b, Hh, Hl);
    gemm_mma<1><<<dim3(HID_/128, TOK/128), 256, GSM>>>(Hh, Hl, W1, fc1_b,
                                                       nullptr, nullptr, Gh, Gl,
                                                       TOK, HID_, DIM_);
    gemm_mma<2><<<dim3(DIM_/128, TOK/128), 256, GSM>>>(Gh, Gl, W2, fc2_b,
                                                       X1, out, nullptr, nullptr,
                                                       TOK, DIM_, HID_);
}

// round 16
// speedup vs baseline: 7.4495x; 1.7955x over previous
#include <cuda_runtime.h>
#include <cuda_bf16.h>
#include <cuda_fp16.h>
#include <math.h>
#include <stdint.h>

#define TOK   4096
#define DIM_  1024
#define HID_  4096

// ---------------- scratch (__device__ globals; no allocations) -------------
__device__ float   g_X1  [(size_t)TOK * DIM_];
__device__ __half  g_QKV [(size_t)TOK * 3 * DIM_];
__device__ __half  g_H   [(size_t)TOK * DIM_];
__device__ __half  g_O   [(size_t)TOK * DIM_];
__device__ __half  g_G   [(size_t)TOK * HID_];
__device__ __half  g_Wqkv[(size_t)3 * DIM_ * DIM_];
__device__ __half  g_Wproj[(size_t)DIM_ * DIM_];
__device__ __half  g_Wfc1[(size_t)HID_ * DIM_];
__device__ __half  g_Wfc2[(size_t)DIM_ * HID_];

// ---------------- helpers ---------------------------------------------------
__device__ __forceinline__ uint32_t smem_u32(const void* p) {
    uint32_t a;
    asm("{ .reg .u64 t; cvta.to.shared.u64 t, %1; cvt.u32.u64 %0, t; }"
        : "=r"(a) : "l"(p));
    return a;
}
__device__ __forceinline__ void cp16(uint32_t dst, const void* src) {
    asm volatile("cp.async.cg.shared.global [%0], [%1], 16;" :: "r"(dst), "l"(src));
}
#define CP_COMMIT() asm volatile("cp.async.commit_group;" ::: "memory")
#define CP_WAIT1()  asm volatile("cp.async.wait_group 1;"  ::: "memory")
#define CP_WAIT0()  asm volatile("cp.async.wait_group 0;"  ::: "memory")

#define LDSM4(r, addr) \
    asm volatile("ldmatrix.sync.aligned.m8n8.x4.shared.b16 {%0,%1,%2,%3}, [%4];" \
        : "=r"((r)[0]), "=r"((r)[1]), "=r"((r)[2]), "=r"((r)[3]) : "r"(addr))

#define LDSM4T(r, addr) \
    asm volatile("ldmatrix.sync.aligned.m8n8.x4.trans.shared.b16 {%0,%1,%2,%3}, [%4];" \
        : "=r"((r)[0]), "=r"((r)[1]), "=r"((r)[2]), "=r"((r)[3]) : "r"(addr))

#define MMA_F16(c, a, b) \
    asm volatile("mma.sync.aligned.m16n8k16.row.col.f32.f16.f16.f32 " \
        "{%0,%1,%2,%3}, {%4,%5,%6,%7}, {%8,%9}, {%0,%1,%2,%3};" \
        : "+f"((c)[0]), "+f"((c)[1]), "+f"((c)[2]), "+f"((c)[3]) \
        : "r"((a)[0]), "r"((a)[1]), "r"((a)[2]), "r"((a)[3]), \
          "r"((b)[0]), "r"((b)[1]))

__device__ __forceinline__ uint32_t pack_h2(float v0, float v1) {
    __half2 h2 = __floats2half2_rn(v0, v1);
    return *reinterpret_cast<uint32_t*>(&h2);
}

// ---------------------------------------------------------------------------
// weight conversion: fp32 -> fp16 (all 4 weights, one launch)
// ---------------------------------------------------------------------------
#define NQKV4  (3 * DIM_ * DIM_ / 4)
#define NPROJ4 (DIM_ * DIM_ / 4)
#define NFC14  (HID_ * DIM_ / 4)
#define NFC24  (DIM_ * HID_ / 4)

__global__ void conv_all(const float4* __restrict__ Wq, const float4* __restrict__ Wp,
                         const float4* __restrict__ W1, const float4* __restrict__ W2,
                         uint2* __restrict__ Q, uint2* __restrict__ P,
                         uint2* __restrict__ F1, uint2* __restrict__ F2) {
    int i = blockIdx.x * blockDim.x + threadIdx.x;
    const float4* src; uint2* dst; int j;
    if (i < NQKV4)                               { src = Wq; dst = Q;  j = i; }
    else if ((j = i - NQKV4) < NPROJ4)           { src = Wp; dst = P; }
    else if ((j = i - NQKV4 - NPROJ4) < NFC14)   { src = W1; dst = F1; }
    else { j = i - NQKV4 - NPROJ4 - NFC14; if (j >= NFC24) return;
           src = W2; dst = F2; }
    float4 v = src[j];
    uint2 o;
    o.x = pack_h2(v.x, v.y);
    o.y = pack_h2(v.z, v.w);
    dst[j] = o;
}

// ---------------------------------------------------------------------------
// LayerNorm: one block per row, 256 threads, fp16 out
// ---------------------------------------------------------------------------
__global__ void ln_kernel(const float* __restrict__ x, const float* __restrict__ g,
                          const float* __restrict__ b, __half* __restrict__ out) {
    __shared__ float red[2][8];
    int row = blockIdx.x, tid = threadIdx.x;
    float4 v = ((const float4*)(x + (size_t)row * DIM_))[tid];
    float s  = v.x + v.y + v.z + v.w;
    float sq = v.x*v.x + v.y*v.y + v.z*v.z + v.w*v.w;
    #pragma unroll
    for (int o = 16; o > 0; o >>= 1) {
        s  += __shfl_xor_sync(0xffffffffu, s,  o);
        sq += __shfl_xor_sync(0xffffffffu, sq, o);
    }
    int wid = tid >> 5, lid = tid & 31;
    if (lid == 0) { red[0][wid] = s; red[1][wid] = sq; }
    __syncthreads();
    s = 0.f; sq = 0.f;
    #pragma unroll
    for (int i = 0; i < 8; i++) { s += red[0][i]; sq += red[1][i]; }
    float mean = s * (1.0f / DIM_);
    float var  = sq * (1.0f / DIM_) - mean * mean;
    float rstd = rsqrtf(var + 1e-5f);
    float4 gg = ((const float4*)g)[tid];
    float4 bb = ((const float4*)b)[tid];
    uint2 h;
    h.x = pack_h2((v.x - mean) * rstd * gg.x + bb.x,
                  (v.y - mean) * rstd * gg.y + bb.y);
    h.y = pack_h2((v.z - mean) * rstd * gg.z + bb.z,
                  (v.w - mean) * rstd * gg.w + bb.w);
    *(uint2*)(out + (size_t)row * DIM_ + tid * 4) = h;
}

// ---------------------------------------------------------------------------
// single-fp16 GEMM via mma.sync: C[M,N] = A[M,K] @ B[N,K]^T + bias (+ epi)
//   EPI 0: fp16 C = D + bias
//   EPI 1: fp16 C = gelu(D + bias)
//   EPI 2: fp32 C = D + bias + res
// 128x128 tile, BK=32, 256 threads (2Mx4N warps), cp.async double buffer,
// 2 smem arrays/stage, 2 CTAs/SM.
// ---------------------------------------------------------------------------
#define ROWB   80
#define ARRB   10240      // 128 * 80
#define STAGEB 20480      // 2 arrays

template <int EPI>
__global__ void __launch_bounds__(256, 2)
gemm_mma(const __half* __restrict__ A, const __half* __restrict__ B,
         const float* __restrict__ bias, const float* __restrict__ res,
         float* __restrict__ Cf, __half* __restrict__ Ch,
         int M, int N, int K) {
    extern __shared__ char smem[];
    const uint32_t sb = smem_u32(smem);
    const int tid = threadIdx.x, wid = tid >> 5, lane = tid & 31;
    const int warpM = wid & 1, warpN = wid >> 1;

    const __half* srcs[2] = {A + (size_t)blockIdx.y * 128 * K,
                             B + (size_t)blockIdx.x * 128 * K};

    const int mat = lane >> 3, l = lane & 7;
    const uint32_t a_off = (uint32_t)((warpM * 64 + (mat & 1) * 8 + l) * ROWB + (mat >> 1) * 16);
    const uint32_t b_off = (uint32_t)((warpN * 32 + (mat >> 1) * 8 + l) * ROWB + (mat & 1) * 16);

    float acc[4][4][4];
    #pragma unroll
    for (int mi = 0; mi < 4; mi++)
        #pragma unroll
        for (int ni = 0; ni < 4; ni++)
            #pragma unroll
            for (int q = 0; q < 4; q++) acc[mi][ni][q] = 0.f;

    const int NC = K >> 5;

    auto fill = [&](int buf, int c) {
        #pragma unroll
        for (int arr = 0; arr < 2; arr++) {
            const __half* s = srcs[arr];
            #pragma unroll
            for (int q = 0; q < 2; q++) {
                int idx = tid + q * 256;
                int row = idx >> 2, ch = idx & 3;
                cp16(sb + buf * STAGEB + arr * ARRB + row * ROWB + ch * 16,
                     s + (size_t)row * K + c * 32 + ch * 8);
            }
        }
        CP_COMMIT();
    };

    fill(0, 0);
    for (int c = 0; c < NC; c++) {
        const int buf = c & 1;
        if (c + 1 < NC) fill(buf ^ 1, c + 1); else CP_COMMIT();
        CP_WAIT1();
        __syncthreads();

        const uint32_t As = sb + buf * STAGEB;
        const uint32_t Bs = As + ARRB;

        #pragma unroll
        for (int ks = 0; ks < 2; ks++) {
            uint32_t a[4][4], b[4][2], t0[4], t1[4];
            #pragma unroll
            for (int mi = 0; mi < 4; mi++)
                LDSM4(a[mi], As + a_off + mi * (16 * ROWB) + ks * 32);
            LDSM4(t0, Bs + b_off + ks * 32);
            LDSM4(t1, Bs + b_off + 16 * ROWB + ks * 32);
            b[0][0]=t0[0]; b[0][1]=t0[1]; b[1][0]=t0[2]; b[1][1]=t0[3];
            b[2][0]=t1[0]; b[2][1]=t1[1]; b[3][0]=t1[2]; b[3][1]=t1[3];
            #pragma unroll
            for (int mi = 0; mi < 4; mi++)
                #pragma unroll
                for (int ni = 0; ni < 4; ni++)
                    MMA_F16(acc[mi][ni], a[mi], b[ni]);
        }
        __syncthreads();
    }

    const int r0 = blockIdx.y * 128 + warpM * 64 + (lane >> 2);
    const int cb = blockIdx.x * 128 + warpN * 32 + 2 * (lane & 3);
    float bv[4][2];
    #pragma unroll
    for (int ni = 0; ni < 4; ni++) {
        bv[ni][0] = __ldg(bias + cb + ni * 8);
        bv[ni][1] = __ldg(bias + cb + ni * 8 + 1);
    }
    #pragma unroll
    for (int mi = 0; mi < 4; mi++) {
        #pragma unroll
        for (int ni = 0; ni < 4; ni++) {
            int row = r0 + mi * 16;
            int col = cb + ni * 8;
            float v0 = acc[mi][ni][0] + bv[ni][0];
            float v1 = acc[mi][ni][1] + bv[ni][1];
            float v2 = acc[mi][ni][2] + bv[ni][0];
            float v3 = acc[mi][ni][3] + bv[ni][1];
            size_t o0 = (size_t)row * N + col;
            size_t o1 = (size_t)(row + 8) * N + col;
            if (EPI == 0) {
                *(uint32_t*)(Ch + o0) = pack_h2(v0, v1);
                *(uint32_t*)(Ch + o1) = pack_h2(v2, v3);
            } else if (EPI == 1) {
                v0 = 0.5f * v0 * (1.0f + erff(v0 * 0.70710678118654752f));
                v1 = 0.5f * v1 * (1.0f + erff(v1 * 0.70710678118654752f));
                v2 = 0.5f * v2 * (1.0f + erff(v2 * 0.70710678118654752f));
                v3 = 0.5f * v3 * (1.0f + erff(v3 * 0.70710678118654752f));
                *(uint32_t*)(Ch + o0) = pack_h2(v0, v1);
                *(uint32_t*)(Ch + o1) = pack_h2(v2, v3);
            } else {
                float2 ra = *(const float2*)(res + o0);
                float2 rb = *(const float2*)(res + o1);
                *(float2*)(Cf + o0) = make_float2(v0 + ra.x, v1 + ra.y);
                *(float2*)(Cf + o1) = make_float2(v2 + rb.x, v3 + rb.y);
            }
        }
    }
}

// ---------------------------------------------------------------------------
// Flash attention, single fp16 mma.sync, fp32 accum, 2 CTAs/SM.
// Grid (64 bh, 8 q-tiles), 256 threads, warps 4M x 2N.
// Smem: Q 128x64h @144 (18432), K 128x64h @144 (18432),
//       V 128x64h @144 row-major (trans-ldmatrix at use) (18432),
//       P 128x128h @272 (34816), reductions (~3KB). Total 93184 B.
// softmax scale 0.125 folded into exp.
// ---------------------------------------------------------------------------
#define ROWQ 144
#define ROWP 272
#define OQ  0
#define OK_ 18432
#define OV  36864
#define OP  55296
#define ORMAX 90112
#define ORSUM 91136
#define OMS   92160
#define OLS   92672
#define ATTN_SMEM 93184
#define SCALE 0.125f

__global__ void __launch_bounds__(256, 2)
attn_mma(const __half* __restrict__ QKV, __half* __restrict__ Og) {
    extern __shared__ char sm[];
    const uint32_t sb = smem_u32(sm);
    const int bb = blockIdx.x >> 4, h = blockIdx.x & 15;
    const int q0 = blockIdx.y * 128;
    const int tid = threadIdx.x, wid = tid >> 5, lane = tid & 31;
    const int warpM = wid & 3, warpN = wid >> 2;
    const int mat = lane >> 3, l8 = lane & 7;
    const int quad = lane >> 2, qlane = lane & 3;
    const size_t base = (size_t)bb * 1024 * 3072 + (size_t)h * 64;

    float* rmaxp = (float*)(sm + ORMAX);
    float* rsump = (float*)(sm + ORSUM);
    float* mSp   = (float*)(sm + OMS);
    float* lSp   = (float*)(sm + OLS);

    if (tid < 128) { mSp[tid] = -1e30f; lSp[tid] = 0.f; }

    // Q tile: pure async copy (scale folded into softmax)
    #pragma unroll
    for (int q = 0; q < 4; q++) {
        int i = tid + q * 256;            // 0..1023
        int r = i >> 3, ch = i & 7;
        cp16(sb + OQ + r * ROWQ + ch * 16, QKV + base + (size_t)(q0 + r) * 3072 + ch * 8);
    }
    CP_COMMIT();

    const uint32_t aq_off = (uint32_t)((warpM * 32 + (mat & 1) * 8 + l8) * ROWQ + (mat >> 1) * 16);
    const uint32_t bk_off = (uint32_t)((warpN * 64 + (mat >> 1) * 8 + l8) * ROWQ + (mat & 1) * 16);
    const uint32_t ap_off = (uint32_t)((warpM * 32 + (mat & 1) * 8 + l8) * ROWP + (mat >> 1) * 16);
    const uint32_t bvt_off = (uint32_t)(((mat & 1) * 8 + l8) * ROWQ + ((mat >> 1) * 8 + warpN * 32) * 2);

    float Oacc[2][4][4];
    #pragma unroll
    for (int mi = 0; mi < 2; mi++)
        #pragma unroll
        for (int ni = 0; ni < 4; ni++)
            #pragma unroll
            for (int q = 0; q < 4; q++) Oacc[mi][ni][q] = 0.f;

    for (int kt = 0; kt < 8; kt++) {
        __syncthreads();   // prior iter done reading K/V
        #pragma unroll
        for (int q = 0; q < 4; q++) {
            int i = tid + q * 256;
            int r = i >> 3, ch = i & 7;
            const __half* src = QKV + base + (size_t)(kt * 128 + r) * 3072 + ch * 8;
            cp16(sb + OK_ + r * ROWQ + ch * 16, src + 1024);
            cp16(sb + OV  + r * ROWQ + ch * 16, src + 2048);
        }
        CP_COMMIT();
        CP_WAIT0();
        __syncthreads();

        // ---- S = Q K^T ----
        float S[2][8][4];
        #pragma unroll
        for (int mi = 0; mi < 2; mi++)
            #pragma unroll
            for (int ni = 0; ni < 8; ni++)
                #pragma unroll
                for (int q = 0; q < 4; q++) S[mi][ni][q] = 0.f;

        #pragma unroll
        for (int ks = 0; ks < 4; ks++) {
            uint32_t a[2][4], b[8][2], t0[4];
            #pragma unroll
            for (int mi = 0; mi < 2; mi++)
                LDSM4(a[mi], sb + OQ + aq_off + mi * (16 * ROWQ) + ks * 32);
            #pragma unroll
            for (int nq = 0; nq < 4; nq++) {
                LDSM4(t0, sb + OK_ + bk_off + nq * (16 * ROWQ) + ks * 32);
                b[2*nq][0] = t0[0]; b[2*nq][1] = t0[1];
                b[2*nq+1][0] = t0[2]; b[2*nq+1][1] = t0[3];
            }
            #pragma unroll
            for (int mi = 0; mi < 2; mi++)
                #pragma unroll
                for (int ni = 0; ni < 8; ni++)
                    MMA_F16(S[mi][ni], a[mi], b[ni]);
        }

        // ---- online softmax (scale folded into exp) ----
        float lmax[2][2];
        #pragma unroll
        for (int mi = 0; mi < 2; mi++)
            #pragma unroll
            for (int qh = 0; qh < 2; qh++) {
                float m = S[mi][0][qh*2];
                #pragma unroll
                for (int ni = 0; ni < 8; ni++) {
                    m = fmaxf(m, S[mi][ni][qh*2]);
                    m = fmaxf(m, S[mi][ni][qh*2+1]);
                }
                m = fmaxf(m, __shfl_xor_sync(0xffffffffu, m, 1));
                m = fmaxf(m, __shfl_xor_sync(0xffffffffu, m, 2));
                lmax[mi][qh] = m;
            }
        if (qlane == 0) {
            #pragma unroll
            for (int mi = 0; mi < 2; mi++)
                #pragma unroll
                for (int qh = 0; qh < 2; qh++) {
                    int row = warpM * 32 + mi * 16 + quad + 8 * qh;
                    rmaxp[row * 2 + warpN] = lmax[mi][qh];
                }
        }
        __syncthreads();

        float corr[2][2], mnew[2][2], lsum[2][2];
        #pragma unroll
        for (int mi = 0; mi < 2; mi++)
            #pragma unroll
            for (int qh = 0; qh < 2; qh++) {
                int row = warpM * 32 + mi * 16 + quad + 8 * qh;
                float mn = fmaxf(rmaxp[row * 2], rmaxp[row * 2 + 1]);
                float mold = mSp[row];
                mn = fmaxf(mold, mn);
                mnew[mi][qh] = mn;
                corr[mi][qh] = __expf((mold - mn) * SCALE);
                float s = 0.f;
                #pragma unroll
                for (int ni = 0; ni < 8; ni++) {
                    float p0 = __expf((S[mi][ni][qh*2]   - mn) * SCALE);
                    float p1 = __expf((S[mi][ni][qh*2+1] - mn) * SCALE);
                    s += p0 + p1;
                    int col = warpN * 64 + ni * 8 + 2 * qlane;
                    *(uint32_t*)(sm + OP + row * ROWP + col * 2) = pack_h2(p0, p1);
                }
                s += __shfl_xor_sync(0xffffffffu, s, 1);
                s += __shfl_xor_sync(0xffffffffu, s, 2);
                lsum[mi][qh] = s;
            }
        if (qlane == 0) {
            #pragma unroll
            for (int mi = 0; mi < 2; mi++)
                #pragma unroll
                for (int qh = 0; qh < 2; qh++) {
                    int row = warpM * 32 + mi * 16 + quad + 8 * qh;
                    rsump[row * 2 + warpN] = lsum[mi][qh];
                }
        }
        __syncthreads();
        if (warpN == 0 && qlane == 0) {
            #pragma unroll
            for (int mi = 0; mi < 2; mi++)
                #pragma unroll
                for (int qh = 0; qh < 2; qh++) {
                    int row = warpM * 32 + mi * 16 + quad + 8 * qh;
                    lSp[row] = lSp[row] * corr[mi][qh] + rsump[row * 2] + rsump[row * 2 + 1];
                    mSp[row] = mnew[mi][qh];
                }
        }
        #pragma unroll
        for (int mi = 0; mi < 2; mi++)
            #pragma unroll
            for (int ni = 0; ni < 4; ni++)
                #pragma unroll
                for (int q = 0; q < 4; q++)
                    Oacc[mi][ni][q] *= corr[mi][q >> 1];

        // ---- O += P V  (V row-major, trans-ldmatrix) ----
        #pragma unroll
        for (int ks = 0; ks < 8; ks++) {
            uint32_t p[2][4], vb[4][2], t0[4], t1[4];
            #pragma unroll
            for (int mi = 0; mi < 2; mi++)
                LDSM4(p[mi], sb + OP + ap_off + mi * (16 * ROWP) + ks * 32);
            LDSM4T(t0, sb + OV + bvt_off + ks * (16 * ROWQ));
            LDSM4T(t1, sb + OV + bvt_off + ks * (16 * ROWQ) + 32);   // +16 cols
            vb[0][0]=t0[0]; vb[0][1]=t0[1]; vb[1][0]=t0[2]; vb[1][1]=t0[3];
            vb[2][0]=t1[0]; vb[2][1]=t1[1]; vb[3][0]=t1[2]; vb[3][1]=t1[3];
            #pragma unroll
            for (int mi = 0; mi < 2; mi++)
                #pragma unroll
                for (int ni = 0; ni < 4; ni++)
                    MMA_F16(Oacc[mi][ni], p[mi], vb[ni]);
        }
    }

    __syncthreads();
    #pragma unroll
    for (int mi = 0; mi < 2; mi++)
        #pragma unroll
        for (int qh = 0; qh < 2; qh++) {
            int row = warpM * 32 + mi * 16 + quad + 8 * qh;
            float inv = 1.0f / lSp[row];
            int tok = bb * 1024 + q0 + row;
            #pragma unroll
            for (int ni = 0; ni < 4; ni++) {
                int col = warpN * 32 + ni * 8 + 2 * qlane;
                size_t off = (size_t)tok * 1024 + h * 64 + col;
                *(uint32_t*)(Og + off) = pack_h2(Oacc[mi][ni][qh*2] * inv,
                                                 Oacc[mi][ni][qh*2+1] * inv);
            }
        }
}

// ---------------------------------------------------------------------------
extern "C" void kernel_launch(void* const* d_in, const int* in_sizes, int n_in,
                              void* d_out, int out_size) {
    const float* x      = (const float*)d_in[0];
    const float* ln1_g  = (const float*)d_in[1];
    const float* ln1_b  = (const float*)d_in[2];
    const float* qkv_w  = (const float*)d_in[3];
    const float* qkv_b  = (const float*)d_in[4];
    const float* proj_w = (const float*)d_in[5];
    const float* proj_b = (const float*)d_in[6];
    const float* ln2_g  = (const float*)d_in[7];
    const float* ln2_b  = (const float*)d_in[8];
    const float* fc1_w  = (const float*)d_in[9];
    const float* fc1_b  = (const float*)d_in[10];
    const float* fc2_w  = (const float*)d_in[11];
    const float* fc2_b  = (const float*)d_in[12];
    float* out = (float*)d_out;

    float *X1;
    __half *QKV,*H,*O,*G,*Wq,*Wp,*W1,*W2;
    cudaGetSymbolAddress((void**)&X1,  g_X1);
    cudaGetSymbolAddress((void**)&QKV, g_QKV);
    cudaGetSymbolAddress((void**)&H,   g_H);
    cudaGetSymbolAddress((void**)&O,   g_O);
    cudaGetSymbolAddress((void**)&G,   g_G);
    cudaGetSymbolAddress((void**)&Wq,  g_Wqkv);
    cudaGetSymbolAddress((void**)&Wp,  g_Wproj);
    cudaGetSymbolAddress((void**)&W1,  g_Wfc1);
    cudaGetSymbolAddress((void**)&W2,  g_Wfc2);

    const int GSM = 2 * STAGEB;   // 40960
    cudaFuncSetAttribute(gemm_mma<0>, cudaFuncAttributeMaxDynamicSharedMemorySize, GSM);
    cudaFuncSetAttribute(gemm_mma<1>, cudaFuncAttributeMaxDynamicSharedMemorySize, GSM);
    cudaFuncSetAttribute(gemm_mma<2>, cudaFuncAttributeMaxDynamicSharedMemorySize, GSM);
    cudaFuncSetAttribute(attn_mma, cudaFuncAttributeMaxDynamicSharedMemorySize, ATTN_SMEM);

    {
        int total = NQKV4 + NPROJ4 + NFC14 + NFC24;
        conv_all<<<(total + 255) / 256, 256>>>(
            (const float4*)qkv_w, (const float4*)proj_w,
            (const float4*)fc1_w, (const float4*)fc2_w,
            (uint2*)Wq, (uint2*)Wp, (uint2*)W1, (uint2*)W2);
    }

    // 1) LN1 -> H (fp16)
    ln_kernel<<<TOK, 256>>>(x, ln1_g, ln1_b, H);
    // 2) QKV = H @ qkv_w^T + b (fp16 out)
    gemm_mma<0><<<dim3(3072/128, TOK/128), 256, GSM>>>(H, Wq, qkv_b,
                                                       nullptr, nullptr, QKV,
                                                       TOK, 3072, DIM_);
    // 3) attention -> O (fp16)
    attn_mma<<<dim3(64, 8), 256, ATTN_SMEM>>>(QKV, O);
    // 4) X1 = x + O @ proj_w^T + b (fp32)
    gemm_mma<2><<<dim3(DIM_/128, TOK/128), 256, GSM>>>(O, Wp, proj_b,
                                                       x, X1, nullptr,
                                                       TOK, DIM_, DIM_);
    // 5) LN2 -> H
    ln_kernel<<<TOK, 256>>>(X1, ln2_g, ln2_b, H);
    // 6) G = gelu(H @ fc1_w^T + b) (fp16)
    gemm_mma<1><<<dim3(HID_/128, TOK/128), 256, GSM>>>(H, W1, fc1_b,
                                                       nullptr, nullptr, G,
                                                       TOK, HID_, DIM_);
    // 7) out = X1 + G @ fc2_w^T + b (fp32)
    gemm_mma<2><<<dim3(DIM_/128, TOK/128), 256, GSM>>>(G, W2, fc2_b,
                                                       X1, out, nullptr,
                                                       TOK, DIM_, HID_);
}

// round 17
// speedup vs baseline: 8.5836x; 1.1522x over previous
#include <cuda_runtime.h>
#include <cuda_bf16.h>
#include <cuda_fp16.h>
#include <math.h>
#include <stdint.h>

#define TOK   4096
#define DIM_  1024
#define HID_  4096

// ---------------- scratch (__device__ globals; no allocations) -------------
__device__ float   g_X1  [(size_t)TOK * DIM_];
__device__ __half  g_QKV [(size_t)TOK * 3 * DIM_];
__device__ __half  g_H   [(size_t)TOK * DIM_];
__device__ __half  g_O   [(size_t)TOK * DIM_];
__device__ __half  g_G   [(size_t)TOK * HID_];
__device__ __half  g_Wqkv[(size_t)3 * DIM_ * DIM_];
__device__ __half  g_Wproj[(size_t)DIM_ * DIM_];
__device__ __half  g_Wfc1[(size_t)HID_ * DIM_];
__device__ __half  g_Wfc2[(size_t)DIM_ * HID_];

// ---------------- helpers ---------------------------------------------------
__device__ __forceinline__ uint32_t smem_u32(const void* p) {
    uint32_t a;
    asm("{ .reg .u64 t; cvta.to.shared.u64 t, %1; cvt.u32.u64 %0, t; }"
        : "=r"(a) : "l"(p));
    return a;
}
__device__ __forceinline__ void cp16(uint32_t dst, const void* src) {
    asm volatile("cp.async.cg.shared.global [%0], [%1], 16;" :: "r"(dst), "l"(src));
}
#define CP_COMMIT() asm volatile("cp.async.commit_group;" ::: "memory")
#define CP_WAIT1()  asm volatile("cp.async.wait_group 1;"  ::: "memory")
#define CP_WAIT0()  asm volatile("cp.async.wait_group 0;"  ::: "memory")

#define LDSM4(r, addr) \
    asm volatile("ldmatrix.sync.aligned.m8n8.x4.shared.b16 {%0,%1,%2,%3}, [%4];" \
        : "=r"((r)[0]), "=r"((r)[1]), "=r"((r)[2]), "=r"((r)[3]) : "r"(addr))

#define LDSM4T(r, addr) \
    asm volatile("ldmatrix.sync.aligned.m8n8.x4.trans.shared.b16 {%0,%1,%2,%3}, [%4];" \
        : "=r"((r)[0]), "=r"((r)[1]), "=r"((r)[2]), "=r"((r)[3]) : "r"(addr))

#define MMA_F16(c, a, b) \
    asm volatile("mma.sync.aligned.m16n8k16.row.col.f32.f16.f16.f32 " \
        "{%0,%1,%2,%3}, {%4,%5,%6,%7}, {%8,%9}, {%0,%1,%2,%3};" \
        : "+f"((c)[0]), "+f"((c)[1]), "+f"((c)[2]), "+f"((c)[3]) \
        : "r"((a)[0]), "r"((a)[1]), "r"((a)[2]), "r"((a)[3]), \
          "r"((b)[0]), "r"((b)[1]))

__device__ __forceinline__ uint32_t pack_h2(float v0, float v1) {
    __half2 h2 = __floats2half2_rn(v0, v1);
    return *reinterpret_cast<uint32_t*>(&h2);
}

// ---------------------------------------------------------------------------
// weight conversion: fp32 -> fp16 (all 4 weights, one launch)
// ---------------------------------------------------------------------------
#define NQKV4  (3 * DIM_ * DIM_ / 4)
#define NPROJ4 (DIM_ * DIM_ / 4)
#define NFC14  (HID_ * DIM_ / 4)
#define NFC24  (DIM_ * HID_ / 4)

__global__ void conv_all(const float4* __restrict__ Wq, const float4* __restrict__ Wp,
                         const float4* __restrict__ W1, const float4* __restrict__ W2,
                         uint2* __restrict__ Q, uint2* __restrict__ P,
                         uint2* __restrict__ F1, uint2* __restrict__ F2) {
    int i = blockIdx.x * blockDim.x + threadIdx.x;
    const float4* src; uint2* dst; int j;
    if (i < NQKV4)                               { src = Wq; dst = Q;  j = i; }
    else if ((j = i - NQKV4) < NPROJ4)           { src = Wp; dst = P; }
    else if ((j = i - NQKV4 - NPROJ4) < NFC14)   { src = W1; dst = F1; }
    else { j = i - NQKV4 - NPROJ4 - NFC14; if (j >= NFC24) return;
           src = W2; dst = F2; }
    float4 v = src[j];
    uint2 o;
    o.x = pack_h2(v.x, v.y);
    o.y = pack_h2(v.z, v.w);
    dst[j] = o;
}

// ---------------------------------------------------------------------------
// LayerNorm: one block per row, 256 threads, fp16 out
// ---------------------------------------------------------------------------
__global__ void ln_kernel(const float* __restrict__ x, const float* __restrict__ g,
                          const float* __restrict__ b, __half* __restrict__ out) {
    __shared__ float red[2][8];
    int row = blockIdx.x, tid = threadIdx.x;
    float4 v = ((const float4*)(x + (size_t)row * DIM_))[tid];
    float s  = v.x + v.y + v.z + v.w;
    float sq = v.x*v.x + v.y*v.y + v.z*v.z + v.w*v.w;
    #pragma unroll
    for (int o = 16; o > 0; o >>= 1) {
        s  += __shfl_xor_sync(0xffffffffu, s,  o);
        sq += __shfl_xor_sync(0xffffffffu, sq, o);
    }
    int wid = tid >> 5, lid = tid & 31;
    if (lid == 0) { red[0][wid] = s; red[1][wid] = sq; }
    __syncthreads();
    s = 0.f; sq = 0.f;
    #pragma unroll
    for (int i = 0; i < 8; i++) { s += red[0][i]; sq += red[1][i]; }
    float mean = s * (1.0f / DIM_);
    float var  = sq * (1.0f / DIM_) - mean * mean;
    float rstd = rsqrtf(var + 1e-5f);
    float4 gg = ((const float4*)g)[tid];
    float4 bb = ((const float4*)b)[tid];
    uint2 h;
    h.x = pack_h2((v.x - mean) * rstd * gg.x + bb.x,
                  (v.y - mean) * rstd * gg.y + bb.y);
    h.y = pack_h2((v.z - mean) * rstd * gg.z + bb.z,
                  (v.w - mean) * rstd * gg.w + bb.w);
    *(uint2*)(out + (size_t)row * DIM_ + tid * 4) = h;
}

// ---------------------------------------------------------------------------
// single-fp16 GEMM via mma.sync: C[M,N] = A[M,K] @ B[N,K]^T + bias (+ epi)
//   EPI 0: fp16 C = D + bias | EPI 1: fp16 gelu | EPI 2: fp32 D + bias + res
// 128x128 tile, BK=64 (half the barriers of BK=32), 256 threads (2Mx4N),
// cp.async double buffer, register double-buffered fragments, 2 CTAs/SM.
// Smem rows: 64 fp16 = 128B data + 16B pad = 144B stride (conflict-free).
// ---------------------------------------------------------------------------
#define ROWB   144
#define ARRB   18432      // 128 * 144
#define STAGEB 36864      // 2 arrays

template <int EPI>
__global__ void __launch_bounds__(256, 2)
gemm_mma(const __half* __restrict__ A, const __half* __restrict__ B,
         const float* __restrict__ bias, const float* __restrict__ res,
         float* __restrict__ Cf, __half* __restrict__ Ch,
         int M, int N, int K) {
    extern __shared__ char smem[];
    const uint32_t sb = smem_u32(smem);
    const int tid = threadIdx.x, wid = tid >> 5, lane = tid & 31;
    const int warpM = wid & 1, warpN = wid >> 1;

    const __half* srcs[2] = {A + (size_t)blockIdx.y * 128 * K,
                             B + (size_t)blockIdx.x * 128 * K};

    const int mat = lane >> 3, l = lane & 7;
    const uint32_t a_off = (uint32_t)((warpM * 64 + (mat & 1) * 8 + l) * ROWB + (mat >> 1) * 16);
    const uint32_t b_off = (uint32_t)((warpN * 32 + (mat >> 1) * 8 + l) * ROWB + (mat & 1) * 16);

    float acc[4][4][4];
    #pragma unroll
    for (int mi = 0; mi < 4; mi++)
        #pragma unroll
        for (int ni = 0; ni < 4; ni++)
            #pragma unroll
            for (int q = 0; q < 4; q++) acc[mi][ni][q] = 0.f;

    const int NC = K >> 6;

    auto fill = [&](int buf, int c) {
        #pragma unroll
        for (int arr = 0; arr < 2; arr++) {
            const __half* s = srcs[arr];
            #pragma unroll
            for (int q = 0; q < 4; q++) {
                int idx = tid + q * 256;             // 0..1023
                int row = idx >> 3, ch = idx & 7;    // 8 chunks of 16B = 128B row
                cp16(sb + buf * STAGEB + arr * ARRB + row * ROWB + ch * 16,
                     s + (size_t)row * K + c * 64 + ch * 8);
            }
        }
        CP_COMMIT();
    };

    // double-buffered fragments (register level)
    uint32_t a2[2][4][4], b2[2][4][2];

    auto ldfrag = [&](int d, int ks, uint32_t As, uint32_t Bs) {
        #pragma unroll
        for (int mi = 0; mi < 4; mi++)
            LDSM4(a2[d][mi], As + a_off + mi * (16 * ROWB) + ks * 32);
        uint32_t t0[4], t1[4];
        LDSM4(t0, Bs + b_off + ks * 32);
        LDSM4(t1, Bs + b_off + 16 * ROWB + ks * 32);
        b2[d][0][0]=t0[0]; b2[d][0][1]=t0[1]; b2[d][1][0]=t0[2]; b2[d][1][1]=t0[3];
        b2[d][2][0]=t1[0]; b2[d][2][1]=t1[1]; b2[d][3][0]=t1[2]; b2[d][3][1]=t1[3];
    };

    fill(0, 0);
    for (int c = 0; c < NC; c++) {
        const int buf = c & 1;
        if (c + 1 < NC) fill(buf ^ 1, c + 1); else CP_COMMIT();
        CP_WAIT1();
        __syncthreads();

        const uint32_t As = sb + buf * STAGEB;
        const uint32_t Bs = As + ARRB;

        ldfrag(0, 0, As, Bs);
        #pragma unroll
        for (int ks = 0; ks < 4; ks++) {
            const int cur = ks & 1;
            if (ks < 3) ldfrag(cur ^ 1, ks + 1, As, Bs);
            #pragma unroll
            for (int mi = 0; mi < 4; mi++)
                #pragma unroll
                for (int ni = 0; ni < 4; ni++)
                    MMA_F16(acc[mi][ni], a2[cur][mi], b2[cur][ni]);
        }
        __syncthreads();
    }

    const int r0 = blockIdx.y * 128 + warpM * 64 + (lane >> 2);
    const int cb = blockIdx.x * 128 + warpN * 32 + 2 * (lane & 3);
    float bv[4][2];
    #pragma unroll
    for (int ni = 0; ni < 4; ni++) {
        bv[ni][0] = __ldg(bias + cb + ni * 8);
        bv[ni][1] = __ldg(bias + cb + ni * 8 + 1);
    }
    #pragma unroll
    for (int mi = 0; mi < 4; mi++) {
        #pragma unroll
        for (int ni = 0; ni < 4; ni++) {
            int row = r0 + mi * 16;
            int col = cb + ni * 8;
            float v0 = acc[mi][ni][0] + bv[ni][0];
            float v1 = acc[mi][ni][1] + bv[ni][1];
            float v2 = acc[mi][ni][2] + bv[ni][0];
            float v3 = acc[mi][ni][3] + bv[ni][1];
            size_t o0 = (size_t)row * N + col;
            size_t o1 = (size_t)(row + 8) * N + col;
            if (EPI == 0) {
                *(uint32_t*)(Ch + o0) = pack_h2(v0, v1);
                *(uint32_t*)(Ch + o1) = pack_h2(v2, v3);
            } else if (EPI == 1) {
                v0 = 0.5f * v0 * (1.0f + erff(v0 * 0.70710678118654752f));
                v1 = 0.5f * v1 * (1.0f + erff(v1 * 0.70710678118654752f));
                v2 = 0.5f * v2 * (1.0f + erff(v2 * 0.70710678118654752f));
                v3 = 0.5f * v3 * (1.0f + erff(v3 * 0.70710678118654752f));
                *(uint32_t*)(Ch + o0) = pack_h2(v0, v1);
                *(uint32_t*)(Ch + o1) = pack_h2(v2, v3);
            } else {
                float2 ra = *(const float2*)(res + o0);
                float2 rb = *(const float2*)(res + o1);
                *(float2*)(Cf + o0) = make_float2(v0 + ra.x, v1 + ra.y);
                *(float2*)(Cf + o1) = make_float2(v2 + rb.x, v3 + rb.y);
            }
        }
    }
}

// ---------------------------------------------------------------------------
// Flash attention, single fp16 mma.sync, fp32 accum, 2 CTAs/SM.
// (unchanged from round 16 — proven at 84us)
// ---------------------------------------------------------------------------
#define ROWQ 144
#define ROWP 272
#define OQ  0
#define OK_ 18432
#define OV  36864
#define OP  55296
#define ORMAX 90112
#define ORSUM 91136
#define OMS   92160
#define OLS   92672
#define ATTN_SMEM 93184
#define SCALE 0.125f

__global__ void __launch_bounds__(256, 2)
attn_mma(const __half* __restrict__ QKV, __half* __restrict__ Og) {
    extern __shared__ char sm[];
    const uint32_t sb = smem_u32(sm);
    const int bb = blockIdx.x >> 4, h = blockIdx.x & 15;
    const int q0 = blockIdx.y * 128;
    const int tid = threadIdx.x, wid = tid >> 5, lane = tid & 31;
    const int warpM = wid & 3, warpN = wid >> 2;
    const int mat = lane >> 3, l8 = lane & 7;
    const int quad = lane >> 2, qlane = lane & 3;
    const size_t base = (size_t)bb * 1024 * 3072 + (size_t)h * 64;

    float* rmaxp = (float*)(sm + ORMAX);
    float* rsump = (float*)(sm + ORSUM);
    float* mSp   = (float*)(sm + OMS);
    float* lSp   = (float*)(sm + OLS);

    if (tid < 128) { mSp[tid] = -1e30f; lSp[tid] = 0.f; }

    #pragma unroll
    for (int q = 0; q < 4; q++) {
        int i = tid + q * 256;
        int r = i >> 3, ch = i & 7;
        cp16(sb + OQ + r * ROWQ + ch * 16, QKV + base + (size_t)(q0 + r) * 3072 + ch * 8);
    }
    CP_COMMIT();

    const uint32_t aq_off = (uint32_t)((warpM * 32 + (mat & 1) * 8 + l8) * ROWQ + (mat >> 1) * 16);
    const uint32_t bk_off = (uint32_t)((warpN * 64 + (mat >> 1) * 8 + l8) * ROWQ + (mat & 1) * 16);
    const uint32_t ap_off = (uint32_t)((warpM * 32 + (mat & 1) * 8 + l8) * ROWP + (mat >> 1) * 16);
    const uint32_t bvt_off = (uint32_t)(((mat & 1) * 8 + l8) * ROWQ + ((mat >> 1) * 8 + warpN * 32) * 2);

    float Oacc[2][4][4];
    #pragma unroll
    for (int mi = 0; mi < 2; mi++)
        #pragma unroll
        for (int ni = 0; ni < 4; ni++)
            #pragma unroll
            for (int q = 0; q < 4; q++) Oacc[mi][ni][q] = 0.f;

    for (int kt = 0; kt < 8; kt++) {
        __syncthreads();
        #pragma unroll
        for (int q = 0; q < 4; q++) {
            int i = tid + q * 256;
            int r = i >> 3, ch = i & 7;
            const __half* src = QKV + base + (size_t)(kt * 128 + r) * 3072 + ch * 8;
            cp16(sb + OK_ + r * ROWQ + ch * 16, src + 1024);
            cp16(sb + OV  + r * ROWQ + ch * 16, src + 2048);
        }
        CP_COMMIT();
        CP_WAIT0();
        __syncthreads();

        float S[2][8][4];
        #pragma unroll
        for (int mi = 0; mi < 2; mi++)
            #pragma unroll
            for (int ni = 0; ni < 8; ni++)
                #pragma unroll
                for (int q = 0; q < 4; q++) S[mi][ni][q] = 0.f;

        #pragma unroll
        for (int ks = 0; ks < 4; ks++) {
            uint32_t a[2][4], b[8][2], t0[4];
            #pragma unroll
            for (int mi = 0; mi < 2; mi++)
                LDSM4(a[mi], sb + OQ + aq_off + mi * (16 * ROWQ) + ks * 32);
            #pragma unroll
            for (int nq = 0; nq < 4; nq++) {
                LDSM4(t0, sb + OK_ + bk_off + nq * (16 * ROWQ) + ks * 32);
                b[2*nq][0] = t0[0]; b[2*nq][1] = t0[1];
                b[2*nq+1][0] = t0[2]; b[2*nq+1][1] = t0[3];
            }
            #pragma unroll
            for (int mi = 0; mi < 2; mi++)
                #pragma unroll
                for (int ni = 0; ni < 8; ni++)
                    MMA_F16(S[mi][ni], a[mi], b[ni]);
        }

        float lmax[2][2];
        #pragma unroll
        for (int mi = 0; mi < 2; mi++)
            #pragma unroll
            for (int qh = 0; qh < 2; qh++) {
                float m = S[mi][0][qh*2];
                #pragma unroll
                for (int ni = 0; ni < 8; ni++) {
                    m = fmaxf(m, S[mi][ni][qh*2]);
                    m = fmaxf(m, S[mi][ni][qh*2+1]);
                }
                m = fmaxf(m, __shfl_xor_sync(0xffffffffu, m, 1));
                m = fmaxf(m, __shfl_xor_sync(0xffffffffu, m, 2));
                lmax[mi][qh] = m;
            }
        if (qlane == 0) {
            #pragma unroll
            for (int mi = 0; mi < 2; mi++)
                #pragma unroll
                for (int qh = 0; qh < 2; qh++) {
                    int row = warpM * 32 + mi * 16 + quad + 8 * qh;
                    rmaxp[row * 2 + warpN] = lmax[mi][qh];
                }
        }
        __syncthreads();

        float corr[2][2], mnew[2][2], lsum[2][2];
        #pragma unroll
        for (int mi = 0; mi < 2; mi++)
            #pragma unroll
            for (int qh = 0; qh < 2; qh++) {
                int row = warpM * 32 + mi * 16 + quad + 8 * qh;
                float mn = fmaxf(rmaxp[row * 2], rmaxp[row * 2 + 1]);
                float mold = mSp[row];
                mn = fmaxf(mold, mn);
                mnew[mi][qh] = mn;
                corr[mi][qh] = __expf((mold - mn) * SCALE);
                float s = 0.f;
                #pragma unroll
                for (int ni = 0; ni < 8; ni++) {
                    float p0 = __expf((S[mi][ni][qh*2]   - mn) * SCALE);
                    float p1 = __expf((S[mi][ni][qh*2+1] - mn) * SCALE);
                    s += p0 + p1;
                    int col = warpN * 64 + ni * 8 + 2 * qlane;
                    *(uint32_t*)(sm + OP + row * ROWP + col * 2) = pack_h2(p0, p1);
                }
                s += __shfl_xor_sync(0xffffffffu, s, 1);
                s += __shfl_xor_sync(0xffffffffu, s, 2);
                lsum[mi][qh] = s;
            }
        if (qlane == 0) {
            #pragma unroll
            for (int mi = 0; mi < 2; mi++)
                #pragma unroll
                for (int qh = 0; qh < 2; qh++) {
                    int row = warpM * 32 + mi * 16 + quad + 8 * qh;
                    rsump[row * 2 + warpN] = lsum[mi][qh];
                }
        }
        __syncthreads();
        if (warpN == 0 && qlane == 0) {
            #pragma unroll
            for (int mi = 0; mi < 2; mi++)
                #pragma unroll
                for (int qh = 0; qh < 2; qh++) {
                    int row = warpM * 32 + mi * 16 + quad + 8 * qh;
                    lSp[row] = lSp[row] * corr[mi][qh] + rsump[row * 2] + rsump[row * 2 + 1];
                    mSp[row] = mnew[mi][qh];
                }
        }
        #pragma unroll
        for (int mi = 0; mi < 2; mi++)
            #pragma unroll
            for (int ni = 0; ni < 4; ni++)
                #pragma unroll
                for (int q = 0; q < 4; q++)
                    Oacc[mi][ni][q] *= corr[mi][q >> 1];

        #pragma unroll
        for (int ks = 0; ks < 8; ks++) {
            uint32_t p[2][4], vb[4][2], t0[4], t1[4];
            #pragma unroll
            for (int mi = 0; mi < 2; mi++)
                LDSM4(p[mi], sb + OP + ap_off + mi * (16 * ROWP) + ks * 32);
            LDSM4T(t0, sb + OV + bvt_off + ks * (16 * ROWQ));
            LDSM4T(t1, sb + OV + bvt_off + ks * (16 * ROWQ) + 32);
            vb[0][0]=t0[0]; vb[0][1]=t0[1]; vb[1][0]=t0[2]; vb[1][1]=t0[3];
            vb[2][0]=t1[0]; vb[2][1]=t1[1]; vb[3][0]=t1[2]; vb[3][1]=t1[3];
            #pragma unroll
            for (int mi = 0; mi < 2; mi++)
                #pragma unroll
                for (int ni = 0; ni < 4; ni++)
                    MMA_F16(Oacc[mi][ni], p[mi], vb[ni]);
        }
    }

    __syncthreads();
    #pragma unroll
    for (int mi = 0; mi < 2; mi++)
        #pragma unroll
        for (int qh = 0; qh < 2; qh++) {
            int row = warpM * 32 + mi * 16 + quad + 8 * qh;
            float inv = 1.0f / lSp[row];
            int tok = bb * 1024 + q0 + row;
            #pragma unroll
            for (int ni = 0; ni < 4; ni++) {
                int col = warpN * 32 + ni * 8 + 2 * qlane;
                size_t off = (size_t)tok * 1024 + h * 64 + col;
                *(uint32_t*)(Og + off) = pack_h2(Oacc[mi][ni][qh*2] * inv,
                                                 Oacc[mi][ni][qh*2+1] * inv);
            }
        }
}

// ---------------------------------------------------------------------------
extern "C" void kernel_launch(void* const* d_in, const int* in_sizes, int n_in,
                              void* d_out, int out_size) {
    const float* x      = (const float*)d_in[0];
    const float* ln1_g  = (const float*)d_in[1];
    const float* ln1_b  = (const float*)d_in[2];
    const float* qkv_w  = (const float*)d_in[3];
    const float* qkv_b  = (const float*)d_in[4];
    const float* proj_w = (const float*)d_in[5];
    const float* proj_b = (const float*)d_in[6];
    const float* ln2_g  = (const float*)d_in[7];
    const float* ln2_b  = (const float*)d_in[8];
    const float* fc1_w  = (const float*)d_in[9];
    const float* fc1_b  = (const float*)d_in[10];
    const float* fc2_w  = (const float*)d_in[11];
    const float* fc2_b  = (const float*)d_in[12];
    float* out = (float*)d_out;

    float *X1;
    __half *QKV,*H,*O,*G,*Wq,*Wp,*W1,*W2;
    cudaGetSymbolAddress((void**)&X1,  g_X1);
    cudaGetSymbolAddress((void**)&QKV, g_QKV);
    cudaGetSymbolAddress((void**)&H,   g_H);
    cudaGetSymbolAddress((void**)&O,   g_O);
    cudaGetSymbolAddress((void**)&G,   g_G);
    cudaGetSymbolAddress((void**)&Wq,  g_Wqkv);
    cudaGetSymbolAddress((void**)&Wp,  g_Wproj);
    cudaGetSymbolAddress((void**)&W1,  g_Wfc1);
    cudaGetSymbolAddress((void**)&W2,  g_Wfc2);

    const int GSM = 2 * STAGEB;   // 73728
    cudaFuncSetAttribute(gemm_mma<0>, cudaFuncAttributeMaxDynamicSharedMemorySize, GSM);
    cudaFuncSetAttribute(gemm_mma<1>, cudaFuncAttributeMaxDynamicSharedMemorySize, GSM);
    cudaFuncSetAttribute(gemm_mma<2>, cudaFuncAttributeMaxDynamicSharedMemorySize, GSM);
    cudaFuncSetAttribute(attn_mma, cudaFuncAttributeMaxDynamicSharedMemorySize, ATTN_SMEM);

    {
        int total = NQKV4 + NPROJ4 + NFC14 + NFC24;
        conv_all<<<(total + 255) / 256, 256>>>(
            (const float4*)qkv_w, (const float4*)proj_w,
            (const float4*)fc1_w, (const float4*)fc2_w,
            (uint2*)Wq, (uint2*)Wp, (uint2*)W1, (uint2*)W2);
    }

    ln_kernel<<<TOK, 256>>>(x, ln1_g, ln1_b, H);
    gemm_mma<0><<<dim3(3072/128, TOK/128), 256, GSM>>>(H, Wq, qkv_b,
                                                       nullptr, nullptr, QKV,
                                                       TOK, 3072, DIM_);
    attn_mma<<<dim3(64, 8), 256, ATTN_SMEM>>>(QKV, O);
    gemm_mma<2><<<dim3(DIM_/128, TOK/128), 256, GSM>>>(O, Wp, proj_b,
                                                       x, X1, nullptr,
                                                       TOK, DIM_, DIM_);
    ln_kernel<<<TOK, 256>>>(X1, ln2_g, ln2_b, H);
    gemm_mma<1><<<dim3(HID_/128, TOK/128), 256, GSM>>>(H, W1, fc1_b,
                                                       nullptr, nullptr, G,
                                                       TOK, HID_, DIM_);
    gemm_mma<2><<<dim3(DIM_/128, TOK/128), 256, GSM>>>(G, W2, fc2_b,
                                                       X1, out, nullptr,
                                                       TOK, DIM_, HID_);
}